// round 2
// baseline (speedup 1.0000x reference)
#include <cuda_runtime.h>

#define BB 64
#define SS 4096
#define DD 64
#define FF 256

#define INV_SIGMA 0.3535533905932738f   /* 64^-0.25 = 2^-1.5 */
#define INV_SQRT_F 0.0625f              /* 256^-0.5 */
#define TS_KM 256
#define TS_KV 256
#define TS_OUT 32

// ---------------- scratch (device globals: no allocation allowed) ----------
__device__ float        g_mean[BB * DD];        // raw sums of k over S
__device__ float        g_kv  [BB * FF * DD];   // sum_s phi_k[s,f] * v[s,d]
__device__ float        g_ksum[BB * FF];        // sum_s phi_k[s,f]
__device__ unsigned int g_kmax[BB];             // ordered-uint encoded max

typedef unsigned long long u64;

// ---------------- packed f32x2 helpers (FFMA2 path) ------------------------
__device__ __forceinline__ u64 pk2(float lo, float hi) {
    u64 r; asm("mov.b64 %0,{%1,%2};" : "=l"(r) : "f"(lo), "f"(hi)); return r;
}
__device__ __forceinline__ float2 upk2(u64 v) {
    float2 r; asm("mov.b64 {%0,%1},%2;" : "=f"(r.x), "=f"(r.y) : "l"(v)); return r;
}
__device__ __forceinline__ u64 fma2(u64 a, u64 b, u64 c) {
    u64 d; asm("fma.rn.f32x2 %0,%1,%2,%3;" : "=l"(d) : "l"(a), "l"(b), "l"(c)); return d;
}

// ordered-uint encoding for float atomicMax (monotonic for all finite + inf)
__device__ __forceinline__ unsigned enc_max(float x) {
    unsigned b = __float_as_uint(x);
    return (b & 0x80000000u) ? ~b : (b | 0x80000000u);
}
__device__ __forceinline__ float dec_max(unsigned k) {
    return (k & 0x80000000u) ? __uint_as_float(k & 0x7FFFFFFFu)
                             : __uint_as_float(~k);
}

// dot(row[0:64], Wrow) with packed fma, row must be 16B-aligned smem
__device__ __forceinline__ float proj_row(const float* row, const u64* w2) {
    const ulonglong2* kr = (const ulonglong2*)row;
    u64 a0 = 0ull, a1 = 0ull;
#pragma unroll
    for (int i = 0; i < 16; i++) {
        ulonglong2 kk = kr[i];
        a0 = fma2(kk.x, w2[2 * i],     a0);
        a1 = fma2(kk.y, w2[2 * i + 1], a1);
    }
    float2 x = upk2(a0), y = upk2(a1);
    return (x.x + x.y) + (y.x + y.y);
}

__device__ __forceinline__ void load_w_regs(const float* __restrict__ w, int f, u64* w2) {
    const float4* wr = (const float4*)(w + f * DD);
#pragma unroll
    for (int i = 0; i < 16; i++) {
        float4 t = wr[i];
        w2[2 * i]     = pk2(t.x, t.y);
        w2[2 * i + 1] = pk2(t.z, t.w);
    }
}

// ---------------- kernel 0: init scratch ------------------------------------
__global__ void init_kernel() {
    int i = blockIdx.x * 256 + threadIdx.x;
    if (i < BB * FF * DD) g_kv[i]   = 0.0f;
    if (i < BB * FF)      g_ksum[i] = 0.0f;
    if (i < BB * DD)      g_mean[i] = 0.0f;
    if (i < BB)           g_kmax[i] = 0x007FFFFFu;  // enc(-inf)
}

// ---------------- kernel 1: per-(b,d) sum of k over S -----------------------
__global__ void mean_kernel(const float* __restrict__ k) {
    const int b = blockIdx.x;
    const int p = blockIdx.y;                 // 4 S-partitions
    const int d   = threadIdx.x & 63;
    const int sub = threadIdx.x >> 6;         // 0..3
    const float* kp = k + (b * SS + p * 1024) * DD;
    float s = 0.0f;
    for (int r = sub; r < 1024; r += 4) s += kp[r * DD + d];
    __shared__ float sm[4][DD];
    sm[sub][d] = s;
    __syncthreads();
    if (threadIdx.x < DD) {
        float t = sm[0][threadIdx.x] + sm[1][threadIdx.x] +
                  sm[2][threadIdx.x] + sm[3][threadIdx.x];
        atomicAdd(&g_mean[b * DD + threadIdx.x], t);
    }
}

// ---------------- kernel 2: global max of centered-K projection -------------
__global__ void __launch_bounds__(256, 2)
kmax_kernel(const float* __restrict__ k, const float* __restrict__ w) {
    const int b = blockIdx.x, tile = blockIdx.y;
    const int f = threadIdx.x;
    u64 w2[32];
    load_w_regs(w, f, w2);

    __shared__ float meanc[DD];
    __shared__ __align__(16) float kc[16][DD];
    __shared__ float wred[8];
    if (threadIdx.x < DD)
        meanc[threadIdx.x] = g_mean[b * DD + threadIdx.x] * (INV_SIGMA / (float)SS);
    __syncthreads();

    float m = -3.0e38f;
    const float* kb = k + (b * SS + tile * TS_KM) * DD;
    for (int c = 0; c < TS_KM / 16; c++) {
        {
            const int r = threadIdx.x >> 4, seg = threadIdx.x & 15;
            const int off = (c * 16 + r) * DD + seg * 4;
            float4 kk = *(const float4*)(kb + off);
            float4 cc;
            cc.x = kk.x * INV_SIGMA - meanc[seg * 4 + 0];
            cc.y = kk.y * INV_SIGMA - meanc[seg * 4 + 1];
            cc.z = kk.z * INV_SIGMA - meanc[seg * 4 + 2];
            cc.w = kk.w * INV_SIGMA - meanc[seg * 4 + 3];
            *(float4*)&kc[r][seg * 4] = cc;
        }
        __syncthreads();
#pragma unroll 1
        for (int r = 0; r < 16; r++) m = fmaxf(m, proj_row(kc[r], w2));
        __syncthreads();
    }
    // block max
    m = fmaxf(m, __shfl_xor_sync(0xffffffffu, m, 16));
    m = fmaxf(m, __shfl_xor_sync(0xffffffffu, m, 8));
    m = fmaxf(m, __shfl_xor_sync(0xffffffffu, m, 4));
    m = fmaxf(m, __shfl_xor_sync(0xffffffffu, m, 2));
    m = fmaxf(m, __shfl_xor_sync(0xffffffffu, m, 1));
    if ((threadIdx.x & 31) == 0) wred[threadIdx.x >> 5] = m;
    __syncthreads();
    if (threadIdx.x == 0) {
        float mm = wred[0];
#pragma unroll
        for (int i = 1; i < 8; i++) mm = fmaxf(mm, wred[i]);
        atomicMax(&g_kmax[b], enc_max(mm));
    }
}

// ---------------- kernel 3: kv = phi_k^T @ V, ksum = sum phi_k --------------
__global__ void __launch_bounds__(256, 1)
kv_kernel(const float* __restrict__ k, const float* __restrict__ v,
          const float* __restrict__ w) {
    const int b = blockIdx.x, tile = blockIdx.y;
    const int f = threadIdx.x;
    u64 w2[32];
    load_w_regs(w, f, w2);

    __shared__ float meanc[DD];
    __shared__ __align__(16) float kc[16][DD];
    __shared__ __align__(16) float vv[16][DD];
    __shared__ float nsq[16];
    if (threadIdx.x < DD)
        meanc[threadIdx.x] = g_mean[b * DD + threadIdx.x] * (INV_SIGMA / (float)SS);
    const float gmax = dec_max(g_kmax[b]);

    u64 kv2[32];
#pragma unroll
    for (int j = 0; j < 32; j++) kv2[j] = 0ull;
    float ksum = 0.0f;
    __syncthreads();

    const float* kb = k + (b * SS + tile * TS_KV) * DD;
    const float* vb = v + (b * SS + tile * TS_KV) * DD;
    for (int c = 0; c < TS_KV / 16; c++) {
        {
            const int r = threadIdx.x >> 4, seg = threadIdx.x & 15;
            const int off = (c * 16 + r) * DD + seg * 4;
            float4 kk = *(const float4*)(kb + off);
            float4 cc;
            cc.x = kk.x * INV_SIGMA - meanc[seg * 4 + 0];
            cc.y = kk.y * INV_SIGMA - meanc[seg * 4 + 1];
            cc.z = kk.z * INV_SIGMA - meanc[seg * 4 + 2];
            cc.w = kk.w * INV_SIGMA - meanc[seg * 4 + 3];
            *(float4*)&kc[r][seg * 4] = cc;
            *(float4*)&vv[r][seg * 4] = *(const float4*)(vb + off);
            float sq = cc.x * cc.x + cc.y * cc.y + cc.z * cc.z + cc.w * cc.w;
            sq += __shfl_xor_sync(0xffffffffu, sq, 1);
            sq += __shfl_xor_sync(0xffffffffu, sq, 2);
            sq += __shfl_xor_sync(0xffffffffu, sq, 4);
            sq += __shfl_xor_sync(0xffffffffu, sq, 8);
            if (seg == 0) nsq[r] = 0.5f * sq;
        }
        __syncthreads();
#pragma unroll 1
        for (int r = 0; r < 16; r++) {
            float kp  = proj_row(kc[r], w2);
            float phi = __expf(kp - nsq[r] - gmax) * INV_SQRT_F;
            ksum += phi;
            u64 p2 = pk2(phi, phi);
            const ulonglong2* vr = (const ulonglong2*)vv[r];
#pragma unroll
            for (int j = 0; j < 16; j++) {
                ulonglong2 vq = vr[j];
                kv2[2 * j]     = fma2(p2, vq.x, kv2[2 * j]);
                kv2[2 * j + 1] = fma2(p2, vq.y, kv2[2 * j + 1]);
            }
        }
        __syncthreads();
    }
    atomicAdd(&g_ksum[b * FF + f], ksum);
    float* dst = g_kv + (b * FF + f) * DD;
#pragma unroll
    for (int j = 0; j < 32; j++) {
        float2 p = upk2(kv2[j]);
        atomicAdd(dst + 2 * j,     p.x);
        atomicAdd(dst + 2 * j + 1, p.y);
    }
}

// ---------------- kernel 4: phi_q, deno, out = phi_q @ kv / deno ------------
__global__ void __launch_bounds__(256, 2)
out_kernel(const float* __restrict__ q, const float* __restrict__ w,
           float* __restrict__ out) {
    const int b = blockIdx.x;
    const int tile = blockIdx.y;   // S / TS_OUT tiles
    const int f = threadIdx.x;
    u64 w2[32];
    load_w_regs(w, f, w2);

    __shared__ float phi[TS_OUT][FF + 1];
    __shared__ __align__(16) float qs[TS_OUT][DD];
    __shared__ __align__(16) float kvs[16][DD];
    __shared__ float ksum_s[FF];
    __shared__ float nsq[TS_OUT], mrow[TS_OUT], dens[TS_OUT];

    ksum_s[f] = g_ksum[b * FF + f];
    {
        const int r = threadIdx.x >> 3, seg = threadIdx.x & 7;
        const float4* src = (const float4*)(q + (b * SS + tile * TS_OUT + r) * DD + seg * 8);
        float4 a = src[0], c = src[1];
        a.x *= INV_SIGMA; a.y *= INV_SIGMA; a.z *= INV_SIGMA; a.w *= INV_SIGMA;
        c.x *= INV_SIGMA; c.y *= INV_SIGMA; c.z *= INV_SIGMA; c.w *= INV_SIGMA;
        *(float4*)&qs[r][seg * 8]     = a;
        *(float4*)&qs[r][seg * 8 + 4] = c;
        float sq = a.x * a.x + a.y * a.y + a.z * a.z + a.w * a.w +
                   c.x * c.x + c.y * c.y + c.z * c.z + c.w * c.w;
        sq += __shfl_xor_sync(0xffffffffu, sq, 1);
        sq += __shfl_xor_sync(0xffffffffu, sq, 2);
        sq += __shfl_xor_sync(0xffffffffu, sq, 4);
        if (seg == 0) nsq[r] = 0.5f * sq;
    }
    __syncthreads();

    // projection: thread owns column f
#pragma unroll 2
    for (int r = 0; r < TS_OUT; r++) phi[r][f] = proj_row(qs[r], w2);
    __syncthreads();

    // per-row max over f
    {
        const int r = threadIdx.x >> 3, part = threadIdx.x & 7;
        float m = -3.0e38f;
        const float* pr = &phi[r][part * 32];
#pragma unroll
        for (int i = 0; i < 32; i++) m = fmaxf(m, pr[i]);
        m = fmaxf(m, __shfl_xor_sync(0xffffffffu, m, 1));
        m = fmaxf(m, __shfl_xor_sync(0xffffffffu, m, 2));
        m = fmaxf(m, __shfl_xor_sync(0xffffffffu, m, 4));
        if (part == 0) mrow[r] = m;
    }
    __syncthreads();

    // exp in place
#pragma unroll 4
    for (int r = 0; r < TS_OUT; r++)
        phi[r][f] = __expf(phi[r][f] - nsq[r] - mrow[r]) * INV_SQRT_F;
    __syncthreads();

    // deno[r] = max(sum_f phi[r][f]*ksum[f], 1e-4)
    {
        const int r = threadIdx.x >> 3, part = threadIdx.x & 7;
        float s = 0.0f;
        const float* pr = &phi[r][part * 32];
        const float* ks = &ksum_s[part * 32];
#pragma unroll
        for (int i = 0; i < 32; i++) s += pr[i] * ks[i];
        s += __shfl_xor_sync(0xffffffffu, s, 1);
        s += __shfl_xor_sync(0xffffffffu, s, 2);
        s += __shfl_xor_sync(0xffffffffu, s, 4);
        if (part == 0) dens[r] = fmaxf(s, 1e-4f);
    }

    // out tile: thread owns 2 rows x 4 d
    const int rg = threadIdx.x >> 4;   // 0..15
    const int dg = threadIdx.x & 15;   // d = dg*4
    const int r0 = rg * 2, r1 = rg * 2 + 1;
    u64 acc00 = 0ull, acc01 = 0ull, acc10 = 0ull, acc11 = 0ull;
    for (int fc = 0; fc < FF / 16; fc++) {
        {
            const int fr = threadIdx.x >> 4, seg = threadIdx.x & 15;
            *(float4*)&kvs[fr][seg * 4] =
                *(const float4*)(g_kv + (b * FF + fc * 16 + fr) * DD + seg * 4);
        }
        __syncthreads();
#pragma unroll
        for (int ff = 0; ff < 16; ff++) {
            float p0v = phi[r0][fc * 16 + ff];
            float p1v = phi[r1][fc * 16 + ff];
            ulonglong2 kk = *(const ulonglong2*)&kvs[ff][dg * 4];
            u64 p02 = pk2(p0v, p0v), p12 = pk2(p1v, p1v);
            acc00 = fma2(p02, kk.x, acc00);
            acc01 = fma2(p02, kk.y, acc01);
            acc10 = fma2(p12, kk.x, acc10);
            acc11 = fma2(p12, kk.y, acc11);
        }
        __syncthreads();
    }
    const float inv0 = 1.0f / dens[r0];
    const float inv1 = 1.0f / dens[r1];
    float2 a0 = upk2(acc00), a1 = upk2(acc01);
    float2 b0 = upk2(acc10), b1 = upk2(acc11);
    float4 o0 = make_float4(a0.x * inv0, a0.y * inv0, a1.x * inv0, a1.y * inv0);
    float4 o1 = make_float4(b0.x * inv1, b0.y * inv1, b1.x * inv1, b1.y * inv1);
    *(float4*)(out + (b * SS + tile * TS_OUT + r0) * DD + dg * 4) = o0;
    *(float4*)(out + (b * SS + tile * TS_OUT + r1) * DD + dg * 4) = o1;
}

// ---------------- launch ----------------------------------------------------
extern "C" void kernel_launch(void* const* d_in, const int* in_sizes, int n_in,
                              void* d_out, int out_size) {
    const float* q = (const float*)d_in[0];
    const float* k = (const float*)d_in[1];
    const float* v = (const float*)d_in[2];
    const float* w = (const float*)d_in[3];
    float* out = (float*)d_out;

    init_kernel<<<(BB * FF * DD + 255) / 256, 256>>>();
    mean_kernel<<<dim3(BB, 4), 256>>>(k);
    kmax_kernel<<<dim3(BB, SS / TS_KM), 256>>>(k, w);
    kv_kernel<<<dim3(BB, SS / TS_KV), 256>>>(k, v, w);
    out_kernel<<<dim3(BB, SS / TS_OUT), 256>>>(q, w, out);
}

// round 4
// speedup vs baseline: 2.1707x; 2.1707x over previous
#include <cuda_runtime.h>
#include <cuda_bf16.h>

typedef unsigned u32; typedef unsigned long long u64;
#define BB 64
#define SS 4096
#define DD 64
#define FF 256
#define INV_SIGMA 0.3535533905932738f
#define INV_SQRT_F 0.0625f

__device__ float    g_mean[BB * DD];
__device__ float    g_kvT [BB * DD * FF];   // [b][d][f]
__device__ float    g_ksum[BB * FF];
__device__ unsigned g_kmax[BB];

// ---------------- helpers ----------------------------------------------------
__device__ __forceinline__ u32 smem_u32(const void* p) {
    u32 a; asm("{ .reg .u64 t; cvta.to.shared.u64 t, %1; cvt.u32.u64 %0, t; }" : "=r"(a) : "l"(p));
    return a;
}
__device__ __forceinline__ void sts32(u32 a, u32 v) {
    asm volatile("st.shared.b32 [%0], %1;" :: "r"(a), "r"(v) : "memory");
}
__device__ __forceinline__ void sts16(u32 a, unsigned short v) {
    asm volatile("st.shared.u16 [%0], %1;" :: "r"(a), "h"(v) : "memory");
}
// pack (a=even,b=odd) -> bf16x2 hi + residual lo
__device__ __forceinline__ void split2(float a, float b, u32& hi, u32& lo) {
    u32 h; asm("cvt.rn.bf16x2.f32 %0,%1,%2;" : "=r"(h) : "f"(b), "f"(a));
    float ah = __uint_as_float(h << 16), bh = __uint_as_float(h & 0xffff0000u);
    float ar = a - ah, br = b - bh;
    asm("cvt.rn.bf16x2.f32 %0,%1,%2;" : "=r"(lo) : "f"(br), "f"(ar));
    hi = h;
}
__device__ __forceinline__ void split1(float a, unsigned short& hi, unsigned short& lo) {
    __nv_bfloat16 h = __float2bfloat16(a);
    float r = a - __bfloat162float(h);
    hi = __bfloat16_as_ushort(h);
    lo = __bfloat16_as_ushort(__float2bfloat16(r));
}
__device__ __forceinline__ unsigned enc_max(float x) {
    unsigned b = __float_as_uint(x);
    return (b & 0x80000000u) ? ~b : (b | 0x80000000u);
}
__device__ __forceinline__ float dec_max(unsigned k) {
    return (k & 0x80000000u) ? __uint_as_float(k & 0x7FFFFFFFu) : __uint_as_float(~k);
}
__device__ __forceinline__ void ldsm4(u32 a, u32& r0, u32& r1, u32& r2, u32& r3) {
    asm volatile("ldmatrix.sync.aligned.m8n8.x4.shared.b16 {%0,%1,%2,%3}, [%4];"
                 : "=r"(r0), "=r"(r1), "=r"(r2), "=r"(r3) : "r"(a));
}
__device__ __forceinline__ void ldsm2(u32 a, u32& r0, u32& r1) {
    asm volatile("ldmatrix.sync.aligned.m8n8.x2.shared.b16 {%0,%1}, [%2];"
                 : "=r"(r0), "=r"(r1) : "r"(a));
}
__device__ __forceinline__ void mma16816(float* c, u32 a0, u32 a1, u32 a2, u32 a3, u32 b0, u32 b1) {
    asm volatile("mma.sync.aligned.m16n8k16.row.col.f32.bf16.bf16.f32 "
                 "{%0,%1,%2,%3},{%4,%5,%6,%7},{%8,%9},{%0,%1,%2,%3};"
                 : "+f"(c[0]), "+f"(c[1]), "+f"(c[2]), "+f"(c[3])
                 : "r"(a0), "r"(a1), "r"(a2), "r"(a3), "r"(b0), "r"(b1));
}

// stage one 64-float row as bf16 hi(/lo) into pitch-144B tile at row r
__device__ __forceinline__ void stage_row(u32 hB, u32 lB, const float4* src, int r, float scale,
                                          const float* cen, float* nsq_out) {
    u32 rb = (u32)r * 144u;
    float nsq = 0.0f;
#pragma unroll
    for (int i = 0; i < 16; i++) {
        float4 x = src[i];
        float c0 = x.x * scale, c1 = x.y * scale, c2 = x.z * scale, c3 = x.w * scale;
        if (cen) { c0 -= cen[4*i]; c1 -= cen[4*i+1]; c2 -= cen[4*i+2]; c3 -= cen[4*i+3]; }
        nsq += c0*c0 + c1*c1 + c2*c2 + c3*c3;
        u32 h0, l0, h1, l1;
        split2(c0, c1, h0, l0); split2(c2, c3, h1, l1);
        sts32(hB + rb + i * 8u, h0); sts32(hB + rb + i * 8u + 4u, h1);
        if (lB) { sts32(lB + rb + i * 8u, l0); sts32(lB + rb + i * 8u + 4u, l1); }
    }
    if (nsq_out) *nsq_out = 0.5f * nsq;
}

// generic 3(or1)-pass chunk GEMM: acc[2 mt][8 nt][4], A rows at aBase (includes warp row
// offset), B rows at bBase (includes n-chunk offset). k = nk*16 per pass.
__device__ __forceinline__ void mma_chunk(float (&acc)[2][8][4],
                                          const u32* aBase, const u32* bBase,
                                          int npass, int nk, u32 apitch, u32 bpitch) {
    const int lane = threadIdx.x & 31;
    const u32 aoff = (u32)(lane & 15) * apitch + (u32)(lane >> 4) * 16u;
    const u32 boff = (u32)(lane & 15) * bpitch + (u32)(lane >> 4) * 16u;
    for (int p = 0; p < npass; p++) {
        for (int kk = 0; kk < nk; kk++) {
            u32 a[2][4];
#pragma unroll
            for (int mt = 0; mt < 2; mt++)
                ldsm4(aBase[p] + aoff + (u32)mt * 16u * apitch + (u32)kk * 32u,
                      a[mt][0], a[mt][1], a[mt][2], a[mt][3]);
            u32 bfr[8][2];
#pragma unroll
            for (int ntp = 0; ntp < 4; ntp++) {
                u32 r0, r1, r2, r3;
                ldsm4(bBase[p] + boff + (u32)ntp * 16u * bpitch + (u32)kk * 32u, r0, r1, r2, r3);
                bfr[2*ntp][0] = r0; bfr[2*ntp][1] = r2;
                bfr[2*ntp+1][0] = r1; bfr[2*ntp+1][1] = r3;
            }
#pragma unroll
            for (int mt = 0; mt < 2; mt++)
#pragma unroll
                for (int nt = 0; nt < 8; nt++)
                    mma16816(acc[mt][nt], a[mt][0], a[mt][1], a[mt][2], a[mt][3],
                             bfr[nt][0], bfr[nt][1]);
        }
    }
}

// ---------------- init + mean ------------------------------------------------
__global__ void init_kernel() {
    int i = blockIdx.x * 256 + threadIdx.x;
    if (i < BB * DD * FF) g_kvT[i] = 0.0f;
    if (i < BB * FF)      g_ksum[i] = 0.0f;
    if (i < BB * DD)      g_mean[i] = 0.0f;
    if (i < BB)           g_kmax[i] = 0x007FFFFFu;
}
__global__ void mean_kernel(const float* __restrict__ k) {
    const int b = blockIdx.x, p = blockIdx.y;
    const int d = threadIdx.x & 63, sub = threadIdx.x >> 6;
    const float* kp = k + (size_t)(b * SS + p * 1024) * DD;
    float s = 0.0f;
    for (int r = sub; r < 1024; r += 4) s += kp[r * DD + d];
    __shared__ float sm[4][DD];
    sm[sub][d] = s; __syncthreads();
    if (threadIdx.x < DD)
        atomicAdd(&g_mean[b * DD + threadIdx.x],
                  sm[0][threadIdx.x] + sm[1][threadIdx.x] + sm[2][threadIdx.x] + sm[3][threadIdx.x]);
}

// ---------------- kmax: max over Kc @ W^T (1-pass bf16, exactness not needed:
// a global shift of the k-normalizer cancels between KV/ksum and the output) ----
#define KM_WH 0u
#define KM_KH 36864u
#define KM_ME 55296u
#define KM_SMEM (KM_ME + 256u)
__global__ void __launch_bounds__(128, 4)
kmax_kernel(const float* __restrict__ k, const float* __restrict__ w) {
    extern __shared__ __align__(16) char sm[];
    const u32 smb = smem_u32(sm);
    const int tid = threadIdx.x, wid = tid >> 5;
    const int b = blockIdx.x, s0 = blockIdx.y * 128;
    float* meanc = (float*)(sm + KM_ME);
    if (tid < DD) meanc[tid] = g_mean[b * DD + tid] * (INV_SIGMA / (float)SS);
    __syncthreads();
    for (int r = tid; r < FF; r += 128)
        stage_row(smb + KM_WH, 0, (const float4*)(w + r * DD), r, 1.0f, 0, 0);
    stage_row(smb + KM_KH, 0, (const float4*)(k + (size_t)(b * SS + s0 + tid) * DD),
              tid, INV_SIGMA, meanc, 0);
    __syncthreads();
    float mx = -3.0e38f;
    u32 aB[1] = { smb + KM_KH + (u32)(wid * 32) * 144u };
    for (int ch = 0; ch < 4; ch++) {
        float acc[2][8][4];
#pragma unroll
        for (int mt = 0; mt < 2; mt++)
#pragma unroll
            for (int nt = 0; nt < 8; nt++)
#pragma unroll
                for (int j = 0; j < 4; j++) acc[mt][nt][j] = 0.0f;
        u32 bB[1] = { smb + KM_WH + (u32)(ch * 64) * 144u };
        mma_chunk(acc, aB, bB, 1, 4, 144u, 144u);
#pragma unroll
        for (int mt = 0; mt < 2; mt++)
#pragma unroll
            for (int nt = 0; nt < 8; nt++)
#pragma unroll
                for (int j = 0; j < 4; j++) mx = fmaxf(mx, acc[mt][nt][j]);
    }
    mx = fmaxf(mx, __shfl_xor_sync(~0u, mx, 16));
    mx = fmaxf(mx, __shfl_xor_sync(~0u, mx, 8));
    mx = fmaxf(mx, __shfl_xor_sync(~0u, mx, 4));
    mx = fmaxf(mx, __shfl_xor_sync(~0u, mx, 2));
    mx = fmaxf(mx, __shfl_xor_sync(~0u, mx, 1));
    if ((tid & 31) == 0) atomicMax(&g_kmax[b], enc_max(mx));
}

// ---------------- kv: KV[d,f] (+ksum) = (phi_k^T @ [V | 1])^T -----------------
#define KV_WH 0u
#define KV_WL 18432u
#define KV_KH 36864u
#define KV_KL 55296u
#define KV_PTH 73728u
#define KV_PTL 108544u
#define KV_VTH 143360u
#define KV_VTL 162944u
#define KV_ME 182528u
#define KV_NS 182784u
#define KV_SMEM (KV_NS + 512u)
__global__ void __launch_bounds__(128, 1)
kv_kernel(const float* __restrict__ k, const float* __restrict__ v, const float* __restrict__ w) {
    extern __shared__ __align__(16) char sm[];
    const u32 smb = smem_u32(sm);
    const int tid = threadIdx.x, wid = tid >> 5, lane = tid & 31;
    const int b = blockIdx.x, F0 = blockIdx.y * 128;
    float* meanc = (float*)(sm + KV_ME);
    float* nsqs  = (float*)(sm + KV_NS);
    if (tid < DD) meanc[tid] = g_mean[b * DD + tid] * (INV_SIGMA / (float)SS);
    const float gmax = dec_max(g_kmax[b]);
    stage_row(smb + KV_WH, smb + KV_WL, (const float4*)(w + (F0 + tid) * DD), tid, 1.0f, 0, 0);
    // ones rows d=64..71 of V^T (persist across tiles)
    if (tid < 8) {
        u32 rb = (u32)(64 + tid) * 272u;
        for (int s = 0; s < 128; s++) {
            sts16(smb + KV_VTH + rb + 2u * s, (unsigned short)0x3F80u);
            sts16(smb + KV_VTL + rb + 2u * s, (unsigned short)0u);
        }
    }
    __syncthreads();

    float kva[2][9][4];
#pragma unroll
    for (int mt = 0; mt < 2; mt++)
#pragma unroll
        for (int nt = 0; nt < 9; nt++)
#pragma unroll
            for (int j = 0; j < 4; j++) kva[mt][nt][j] = 0.0f;

    for (int t = 0; t < 8; t++) {
        const int s0 = (blockIdx.z * 8 + t) * 128;
        float nsq;
        stage_row(smb + KV_KH, smb + KV_KL,
                  (const float4*)(k + (size_t)(b * SS + s0 + tid) * DD), tid, INV_SIGMA, meanc, &nsq);
        nsqs[tid] = nsq;
        {   // V row -> V^T columns (bf16 hi/lo)
            const float4* vr = (const float4*)(v + (size_t)(b * SS + s0 + tid) * DD);
#pragma unroll
            for (int i = 0; i < 16; i++) {
                float4 x = vr[i];
                unsigned short h0, l0, h1, l1, h2, l2, h3, l3;
                split1(x.x, h0, l0); split1(x.y, h1, l1);
                split1(x.z, h2, l2); split1(x.w, h3, l3);
                u32 cofs = 2u * (u32)tid;
                sts16(smb + KV_VTH + (u32)(4*i+0) * 272u + cofs, h0);
                sts16(smb + KV_VTH + (u32)(4*i+1) * 272u + cofs, h1);
                sts16(smb + KV_VTH + (u32)(4*i+2) * 272u + cofs, h2);
                sts16(smb + KV_VTH + (u32)(4*i+3) * 272u + cofs, h3);
                sts16(smb + KV_VTL + (u32)(4*i+0) * 272u + cofs, l0);
                sts16(smb + KV_VTL + (u32)(4*i+1) * 272u + cofs, l1);
                sts16(smb + KV_VTL + (u32)(4*i+2) * 272u + cofs, l2);
                sts16(smb + KV_VTL + (u32)(4*i+3) * 272u + cofs, l3);
            }
        }
        __syncthreads();
        // proj: warps over s rows; 2 chunks of 64 f; 3-pass
        const u32 aB[3] = { smb + KV_KH + (u32)(wid * 32) * 144u,
                            smb + KV_KH + (u32)(wid * 32) * 144u,
                            smb + KV_KL + (u32)(wid * 32) * 144u };
        for (int ch = 0; ch < 2; ch++) {
            float acc[2][8][4];
#pragma unroll
            for (int mt = 0; mt < 2; mt++)
#pragma unroll
                for (int nt = 0; nt < 8; nt++)
#pragma unroll
                    for (int j = 0; j < 4; j++) acc[mt][nt][j] = 0.0f;
            const u32 bB[3] = { smb + KV_WH + (u32)(ch * 64) * 144u,
                                smb + KV_WL + (u32)(ch * 64) * 144u,
                                smb + KV_WH + (u32)(ch * 64) * 144u };
            mma_chunk(acc, aB, bB, 3, 4, 144u, 144u);
            // exp + scatter phi^T[f][s]
#pragma unroll
            for (int mt = 0; mt < 2; mt++) {
                const int r0 = wid * 32 + mt * 16 + (lane >> 2);
                const float n0 = nsqs[r0] + gmax, n1 = nsqs[r0 + 8] + gmax;
#pragma unroll
                for (int nt = 0; nt < 8; nt++) {
                    const int f = ch * 64 + nt * 8 + (lane & 3) * 2;
                    float p00 = __expf(acc[mt][nt][0] - n0) * INV_SQRT_F;
                    float p01 = __expf(acc[mt][nt][1] - n0) * INV_SQRT_F;
                    float p10 = __expf(acc[mt][nt][2] - n1) * INV_SQRT_F;
                    float p11 = __expf(acc[mt][nt][3] - n1) * INV_SQRT_F;
                    unsigned short h, l;
                    split1(p00, h, l);
                    sts16(smb + KV_PTH + (u32)f * 272u + 2u * r0, h);
                    sts16(smb + KV_PTL + (u32)f * 272u + 2u * r0, l);
                    split1(p01, h, l);
                    sts16(smb + KV_PTH + (u32)(f + 1) * 272u + 2u * r0, h);
                    sts16(smb + KV_PTL + (u32)(f + 1) * 272u + 2u * r0, l);
                    split1(p10, h, l);
                    sts16(smb + KV_PTH + (u32)f * 272u + 2u * (r0 + 8), h);
                    sts16(smb + KV_PTL + (u32)f * 272u + 2u * (r0 + 8), l);
                    split1(p11, h, l);
                    sts16(smb + KV_PTH + (u32)(f + 1) * 272u + 2u * (r0 + 8), h);
                    sts16(smb + KV_PTL + (u32)(f + 1) * 272u + 2u * (r0 + 8), l);
                }
            }
        }
        __syncthreads();
        // kv accumulation: warps over f rows; k = 128 s; n = 72 (9 tiles)
        {
            const u32 aoff = (u32)(lane & 15) * 272u + (u32)(lane >> 4) * 16u;
            const u32 boff = (u32)(lane & 15) * 272u + (u32)(lane >> 4) * 16u;
            const u32 b2off = (u32)(lane & 7) * 272u + (u32)((lane >> 3) & 1) * 16u;
            const u32 APa[3] = { smb + KV_PTH + (u32)(wid * 32) * 272u,
                                 smb + KV_PTH + (u32)(wid * 32) * 272u,
                                 smb + KV_PTL + (u32)(wid * 32) * 272u };
            const u32 BPa[3] = { smb + KV_VTH, smb + KV_VTL, smb + KV_VTH };
            for (int p = 0; p < 3; p++) {
                for (int kk = 0; kk < 8; kk++) {
                    u32 a[2][4];
#pragma unroll
                    for (int mt = 0; mt < 2; mt++)
                        ldsm4(APa[p] + aoff + (u32)mt * 16u * 272u + (u32)kk * 32u,
                              a[mt][0], a[mt][1], a[mt][2], a[mt][3]);
                    u32 bf[9][2];
#pragma unroll
                    for (int ntp = 0; ntp < 4; ntp++) {
                        u32 r0, r1, r2, r3;
                        ldsm4(BPa[p] + boff + (u32)ntp * 16u * 272u + (u32)kk * 32u, r0, r1, r2, r3);
                        bf[2*ntp][0] = r0; bf[2*ntp][1] = r2;
                        bf[2*ntp+1][0] = r1; bf[2*ntp+1][1] = r3;
                    }
                    ldsm2(BPa[p] + b2off + 64u * 272u + (u32)kk * 32u, bf[8][0], bf[8][1]);
#pragma unroll
                    for (int mt = 0; mt < 2; mt++)
#pragma unroll
                        for (int nt = 0; nt < 9; nt++)
                            mma16816(kva[mt][nt], a[mt][0], a[mt][1], a[mt][2], a[mt][3],
                                     bf[nt][0], bf[nt][1]);
                }
            }
        }
        __syncthreads();
    }
    // epilogue: scatter KV^T and ksum
#pragma unroll
    for (int mt = 0; mt < 2; mt++) {
        const int f0 = F0 + wid * 32 + mt * 16 + (lane >> 2);
#pragma unroll
        for (int nt = 0; nt < 9; nt++) {
            const int d = nt * 8 + (lane & 3) * 2;
            if (nt < 8) {
                atomicAdd(g_kvT + ((size_t)b * DD + d)     * FF + f0,      kva[mt][nt][0]);
                atomicAdd(g_kvT + ((size_t)b * DD + d + 1) * FF + f0,      kva[mt][nt][1]);
                atomicAdd(g_kvT + ((size_t)b * DD + d)     * FF + f0 + 8,  kva[mt][nt][2]);
                atomicAdd(g_kvT + ((size_t)b * DD + d + 1) * FF + f0 + 8,  kva[mt][nt][3]);
            } else if ((lane & 3) == 0) {
                atomicAdd(g_ksum + b * FF + f0,     kva[mt][nt][0]);
                atomicAdd(g_ksum + b * FF + f0 + 8, kva[mt][nt][2]);
            }
        }
    }
}

// ---------------- out: phi_q @ KV^T / deno ------------------------------------
#define OU_WH 0u
#define OU_WL 36864u
#define OU_QH 73728u
#define OU_QL 92160u
#define OU_PH 110592u
#define OU_PL 129024u
#define OU_KVH 147456u
#define OU_KVL 181248u
#define OU_KS 215040u
#define OU_NS 216064u
#define OU_RM 216576u
#define OU_DE 217088u
#define OU_SMEM (OU_DE + 512u)
__global__ void __launch_bounds__(128, 1)
out_kernel(const float* __restrict__ q, const float* __restrict__ w, float* __restrict__ out) {
    extern __shared__ __align__(16) char sm[];
    const u32 smb = smem_u32(sm);
    const int tid = threadIdx.x, wid = tid >> 5, lane = tid & 31;
    const int b = blockIdx.x, s0 = blockIdx.y * 128;
    float* ksum_s = (float*)(sm + OU_KS);
    float* nsqs   = (float*)(sm + OU_NS);
    float* rowmax = (float*)(sm + OU_RM);
    float* denos  = (float*)(sm + OU_DE);
    ksum_s[tid]       = g_ksum[b * FF + tid];
    ksum_s[tid + 128] = g_ksum[b * FF + tid + 128];
    stage_row(smb + OU_WH, smb + OU_WL, (const float4*)(w + tid * DD),         tid,       1.0f, 0, 0);
    stage_row(smb + OU_WH, smb + OU_WL, (const float4*)(w + (tid + 128) * DD), tid + 128, 1.0f, 0, 0);
    float nsq;
    stage_row(smb + OU_QH, smb + OU_QL, (const float4*)(q + (size_t)(b * SS + s0 + tid) * DD),
              tid, INV_SIGMA, 0, &nsq);
    nsqs[tid] = nsq;
    {   // KV^T tile [d][f] hi/lo, pitch 528
        const int d = tid >> 1, half = tid & 1;
        const float* src = g_kvT + (size_t)b * DD * FF + d * FF + half * 128;
        u32 rb = (u32)d * 528u + (u32)half * 256u;
#pragma unroll 8
        for (int j = 0; j < 64; j++) {
            u32 hi, lo;
            split2(src[2*j], src[2*j+1], hi, lo);
            sts32(smb + OU_KVH + rb + 4u * j, hi);
            sts32(smb + OU_KVL + rb + 4u * j, lo);
        }
    }
    __syncthreads();

    const u32 aH1[1] = { smb + OU_QH + (u32)(wid * 32) * 144u };
    const u32 aB[3]  = { smb + OU_QH + (u32)(wid * 32) * 144u,
                         smb + OU_QH + (u32)(wid * 32) * 144u,
                         smb + OU_QL + (u32)(wid * 32) * 144u };
    // pass 1: row max (1-pass bf16; per-row shift cancels in num/deno)
    {
        float mx0[2], mx1[2];
        mx0[0] = mx0[1] = mx1[0] = mx1[1] = -3.0e38f;
        for (int ch = 0; ch < 4; ch++) {
            float acc[2][8][4];
#pragma unroll
            for (int mt = 0; mt < 2; mt++)
#pragma unroll
                for (int nt = 0; nt < 8; nt++)
#pragma unroll
                    for (int j = 0; j < 4; j++) acc[mt][nt][j] = 0.0f;
            const u32 bB[1] = { smb + OU_WH + (u32)(ch * 64) * 144u };
            mma_chunk(acc, aH1, bB, 1, 4, 144u, 144u);
#pragma unroll
            for (int mt = 0; mt < 2; mt++)
#pragma unroll
                for (int nt = 0; nt < 8; nt++) {
                    mx0[mt] = fmaxf(mx0[mt], fmaxf(acc[mt][nt][0], acc[mt][nt][1]));
                    mx1[mt] = fmaxf(mx1[mt], fmaxf(acc[mt][nt][2], acc[mt][nt][3]));
                }
        }
#pragma unroll
        for (int mt = 0; mt < 2; mt++) {
            mx0[mt] = fmaxf(mx0[mt], __shfl_xor_sync(~0u, mx0[mt], 1));
            mx0[mt] = fmaxf(mx0[mt], __shfl_xor_sync(~0u, mx0[mt], 2));
            mx1[mt] = fmaxf(mx1[mt], __shfl_xor_sync(~0u, mx1[mt], 1));
            mx1[mt] = fmaxf(mx1[mt], __shfl_xor_sync(~0u, mx1[mt], 2));
            if ((lane & 3) == 0) {
                rowmax[wid * 32 + mt * 16 + (lane >> 2)]     = mx0[mt];
                rowmax[wid * 32 + mt * 16 + (lane >> 2) + 8] = mx1[mt];
            }
        }
    }
    __syncthreads();

    float oacc[2][8][4];
#pragma unroll
    for (int mt = 0; mt < 2; mt++)
#pragma unroll
        for (int nt = 0; nt < 8; nt++)
#pragma unroll
            for (int j = 0; j < 4; j++) oacc[mt][nt][j] = 0.0f;
    float dp0[2] = {0.0f, 0.0f}, dp1[2] = {0.0f, 0.0f};

    for (int ch = 0; ch < 4; ch++) {
        float acc[2][8][4];
#pragma unroll
        for (int mt = 0; mt < 2; mt++)
#pragma unroll
            for (int nt = 0; nt < 8; nt++)
#pragma unroll
                for (int j = 0; j < 4; j++) acc[mt][nt][j] = 0.0f;
        const u32 bB[3] = { smb + OU_WH + (u32)(ch * 64) * 144u,
                            smb + OU_WL + (u32)(ch * 64) * 144u,
                            smb + OU_WH + (u32)(ch * 64) * 144u };
        mma_chunk(acc, aB, bB, 3, 4, 144u, 144u);
        // exp + deno + scatter phi chunk [s][64f]
#pragma unroll
        for (int mt = 0; mt < 2; mt++) {
            const int r0 = wid * 32 + mt * 16 + (lane >> 2);
            const float n0 = nsqs[r0] + rowmax[r0], n1 = nsqs[r0 + 8] + rowmax[r0 + 8];
#pragma unroll
            for (int nt = 0; nt < 8; nt++) {
                const int fl = nt * 8 + (lane & 3) * 2;
                const float ks0 = ksum_s[ch * 64 + fl], ks1 = ksum_s[ch * 64 + fl + 1];
                float p00 = __expf(acc[mt][nt][0] - n0) * INV_SQRT_F;
                float p01 = __expf(acc[mt][nt][1] - n0) * INV_SQRT_F;
                float p10 = __expf(acc[mt][nt][2] - n1) * INV_SQRT_F;
                float p11 = __expf(acc[mt][nt][3] - n1) * INV_SQRT_F;
                dp0[mt] += p00 * ks0 + p01 * ks1;
                dp1[mt] += p10 * ks0 + p11 * ks1;
                u32 hi, lo;
                split2(p00, p01, hi, lo);
                sts32(smb + OU_PH + (u32)r0 * 144u + 2u * fl, hi);
                sts32(smb + OU_PL + (u32)r0 * 144u + 2u * fl, lo);
                split2(p10, p11, hi, lo);
                sts32(smb + OU_PH + (u32)(r0 + 8) * 144u + 2u * fl, hi);
                sts32(smb + OU_PL + (u32)(r0 + 8) * 144u + 2u * fl, lo);
            }
        }
        __syncthreads();
        // out accumulation: A = phi chunk, B = KV^T k-window
        const u32 pA[3] = { smb + OU_PH + (u32)(wid * 32) * 144u,
                            smb + OU_PH + (u32)(wid * 32) * 144u,
                            smb + OU_PL + (u32)(wid * 32) * 144u };
        const u32 pB[3] = { smb + OU_KVH + (u32)(ch * 128), smb + OU_KVL + (u32)(ch * 128),
                            smb + OU_KVH + (u32)(ch * 128) };
        mma_chunk(oacc, pA, pB, 3, 4, 144u, 528u);
        __syncthreads();
    }
    // deno
#pragma unroll
    for (int mt = 0; mt < 2; mt++) {
        dp0[mt] += __shfl_xor_sync(~0u, dp0[mt], 1);
        dp0[mt] += __shfl_xor_sync(~0u, dp0[mt], 2);
        dp1[mt] += __shfl_xor_sync(~0u, dp1[mt], 1);
        dp1[mt] += __shfl_xor_sync(~0u, dp1[mt], 2);
        if ((lane & 3) == 0) {
            denos[wid * 32 + mt * 16 + (lane >> 2)]     = fmaxf(dp0[mt], 1e-4f);
            denos[wid * 32 + mt * 16 + (lane >> 2) + 8] = fmaxf(dp1[mt], 1e-4f);
        }
    }
    __syncthreads();
#pragma unroll
    for (int mt = 0; mt < 2; mt++) {
        const int r0 = wid * 32 + mt * 16 + (lane >> 2);
        const float i0 = 1.0f / denos[r0], i1 = 1.0f / denos[r0 + 8];
#pragma unroll
        for (int nt = 0; nt < 8; nt++) {
            const int d = nt * 8 + (lane & 3) * 2;
            float2 o0 = make_float2(oacc[mt][nt][0] * i0, oacc[mt][nt][1] * i0);
            float2 o1 = make_float2(oacc[mt][nt][2] * i1, oacc[mt][nt][3] * i1);
            *(float2*)(out + (size_t)(b * SS + s0 + r0) * DD + d)     = o0;
            *(float2*)(out + (size_t)(b * SS + s0 + r0 + 8) * DD + d) = o1;
        }
    }
}

// ---------------- launch ------------------------------------------------------
extern "C" void kernel_launch(void* const* d_in, const int* in_sizes, int n_in,
                              void* d_out, int out_size) {
    const float* q = (const float*)d_in[0];
    const float* k = (const float*)d_in[1];
    const float* v = (const float*)d_in[2];
    const float* w = (const float*)d_in[3];
    float* out = (float*)d_out;
    cudaFuncSetAttribute(kmax_kernel, cudaFuncAttributeMaxDynamicSharedMemorySize, KM_SMEM);
    cudaFuncSetAttribute(kv_kernel,   cudaFuncAttributeMaxDynamicSharedMemorySize, KV_SMEM);
    cudaFuncSetAttribute(out_kernel,  cudaFuncAttributeMaxDynamicSharedMemorySize, OU_SMEM);
    init_kernel<<<(BB * DD * FF + 255) / 256, 256>>>();
    mean_kernel<<<dim3(BB, 4), 256>>>(k);
    kmax_kernel<<<dim3(BB, SS / 128), 128, KM_SMEM>>>(k, w);
    kv_kernel<<<dim3(BB, 2, 4), 128, KV_SMEM>>>(k, v, w);
    out_kernel<<<dim3(BB, SS / 128), 128, OU_SMEM>>>(q, w, out);
}

// round 5
// speedup vs baseline: 2.3507x; 1.0829x over previous
#include <cuda_runtime.h>
#include <cuda_bf16.h>

typedef unsigned u32; typedef unsigned long long u64;
#define BB 64
#define SS 4096
#define DD 64
#define FF 256
#define INV_SIGMA 0.3535533905932738f
#define INV_SQRT_F 0.0625f

__device__ float    g_mean[BB * DD];
__device__ float    g_kvT [BB * DD * FF];   // [b][d][f]
__device__ float    g_ksum[BB * FF];
__device__ unsigned g_kmax[BB];

// ---------------- helpers ----------------------------------------------------
__device__ __forceinline__ u32 smem_u32(const void* p) {
    u32 a; asm("{ .reg .u64 t; cvta.to.shared.u64 t, %1; cvt.u32.u64 %0, t; }" : "=r"(a) : "l"(p));
    return a;
}
__device__ __forceinline__ void sts32(u32 a, u32 v) {
    asm volatile("st.shared.b32 [%0], %1;" :: "r"(a), "r"(v) : "memory");
}
__device__ __forceinline__ void sts16(u32 a, unsigned short v) {
    asm volatile("st.shared.u16 [%0], %1;" :: "r"(a), "h"(v) : "memory");
}
__device__ __forceinline__ void split2(float a, float b, u32& hi, u32& lo) {
    u32 h; asm("cvt.rn.bf16x2.f32 %0,%1,%2;" : "=r"(h) : "f"(b), "f"(a));
    float ah = __uint_as_float(h << 16), bh = __uint_as_float(h & 0xffff0000u);
    float ar = a - ah, br = b - bh;
    asm("cvt.rn.bf16x2.f32 %0,%1,%2;" : "=r"(lo) : "f"(br), "f"(ar));
    hi = h;
}
__device__ __forceinline__ void split1(float a, unsigned short& hi, unsigned short& lo) {
    __nv_bfloat16 h = __float2bfloat16(a);
    float r = a - __bfloat162float(h);
    hi = __bfloat16_as_ushort(h);
    lo = __bfloat16_as_ushort(__float2bfloat16(r));
}
__device__ __forceinline__ unsigned enc_max(float x) {
    unsigned b = __float_as_uint(x);
    return (b & 0x80000000u) ? ~b : (b | 0x80000000u);
}
__device__ __forceinline__ float dec_max(unsigned k) {
    return (k & 0x80000000u) ? __uint_as_float(k & 0x7FFFFFFFu) : __uint_as_float(~k);
}
__device__ __forceinline__ void ldsm4(u32 a, u32& r0, u32& r1, u32& r2, u32& r3) {
    asm volatile("ldmatrix.sync.aligned.m8n8.x4.shared.b16 {%0,%1,%2,%3}, [%4];"
                 : "=r"(r0), "=r"(r1), "=r"(r2), "=r"(r3) : "r"(a));
}
__device__ __forceinline__ void ldsm2(u32 a, u32& r0, u32& r1) {
    asm volatile("ldmatrix.sync.aligned.m8n8.x2.shared.b16 {%0,%1}, [%2];"
                 : "=r"(r0), "=r"(r1) : "r"(a));
}
__device__ __forceinline__ void mma16816(float* c, u32 a0, u32 a1, u32 a2, u32 a3, u32 b0, u32 b1) {
    asm volatile("mma.sync.aligned.m16n8k16.row.col.f32.bf16.bf16.f32 "
                 "{%0,%1,%2,%3},{%4,%5,%6,%7},{%8,%9},{%0,%1,%2,%3};"
                 : "+f"(c[0]), "+f"(c[1]), "+f"(c[2]), "+f"(c[3])
                 : "r"(a0), "r"(a1), "r"(a2), "r"(a3), "r"(b0), "r"(b1));
}

// stage one 64-float row as bf16 hi(/lo) into pitch-144B tile at row r
__device__ __forceinline__ void stage_row(u32 hB, u32 lB, const float4* src, int r, float scale,
                                          const float* cen, float* nsq_out) {
    u32 rb = (u32)r * 144u;
    float nsq = 0.0f;
#pragma unroll
    for (int i = 0; i < 16; i++) {
        float4 x = src[i];
        float c0 = x.x * scale, c1 = x.y * scale, c2 = x.z * scale, c3 = x.w * scale;
        if (cen) { c0 -= cen[4*i]; c1 -= cen[4*i+1]; c2 -= cen[4*i+2]; c3 -= cen[4*i+3]; }
        nsq += c0*c0 + c1*c1 + c2*c2 + c3*c3;
        u32 h0, l0, h1, l1;
        split2(c0, c1, h0, l0); split2(c2, c3, h1, l1);
        sts32(hB + rb + i * 8u, h0); sts32(hB + rb + i * 8u + 4u, h1);
        if (lB) { sts32(lB + rb + i * 8u, l0); sts32(lB + rb + i * 8u + 4u, l1); }
    }
    if (nsq_out) *nsq_out = 0.5f * nsq;
}

// 1-mtile chunk GEMM: acc[8 nt][4]; warp m-tile of 16 rows. k = nk*16 per pass.
__device__ __forceinline__ void mma_chunk1(float (&acc)[8][4], const u32* aBase, const u32* bBase,
                                           int npass, int nk, u32 apitch, u32 bpitch) {
    const int lane = threadIdx.x & 31;
    const u32 aoff = (u32)(lane & 15) * apitch + (u32)(lane >> 4) * 16u;
    const u32 boff = (u32)(lane & 15) * bpitch + (u32)(lane >> 4) * 16u;
    for (int p = 0; p < npass; p++) {
        for (int kk = 0; kk < nk; kk++) {
            u32 a0, a1, a2, a3;
            ldsm4(aBase[p] + aoff + (u32)kk * 32u, a0, a1, a2, a3);
            u32 bfr[8][2];
#pragma unroll
            for (int ntp = 0; ntp < 4; ntp++) {
                u32 r0, r1, r2, r3;
                ldsm4(bBase[p] + boff + (u32)ntp * 16u * bpitch + (u32)kk * 32u, r0, r1, r2, r3);
                bfr[2*ntp][0] = r0; bfr[2*ntp][1] = r2;
                bfr[2*ntp+1][0] = r1; bfr[2*ntp+1][1] = r3;
            }
#pragma unroll
            for (int nt = 0; nt < 8; nt++)
                mma16816(acc[nt], a0, a1, a2, a3, bfr[nt][0], bfr[nt][1]);
        }
    }
}

// ---------------- init + mean ------------------------------------------------
__global__ void init_kernel() {
    int i = blockIdx.x * 256 + threadIdx.x;
    if (i < BB * DD * FF) g_kvT[i] = 0.0f;
    if (i < BB * FF)      g_ksum[i] = 0.0f;
    if (i < BB * DD)      g_mean[i] = 0.0f;
    if (i < BB)           g_kmax[i] = 0x007FFFFFu;
}
__global__ void mean_kernel(const float* __restrict__ k) {
    const int b = blockIdx.x, p = blockIdx.y;
    const int d = threadIdx.x & 63, sub = threadIdx.x >> 6;
    const float* kp = k + (size_t)(b * SS + p * 1024) * DD;
    float s = 0.0f;
    for (int r = sub; r < 1024; r += 4) s += kp[r * DD + d];
    __shared__ float sm[4][DD];
    sm[sub][d] = s; __syncthreads();
    if (threadIdx.x < DD)
        atomicAdd(&g_mean[b * DD + threadIdx.x],
                  sm[0][threadIdx.x] + sm[1][threadIdx.x] + sm[2][threadIdx.x] + sm[3][threadIdx.x]);
}

// ---------------- kmax: max over Kc @ W^T (1-pass bf16; shift cancels exactly) -
#define KM_WH 0u
#define KM_KH 36864u
#define KM_ME 55296u
#define KM_SMEM (KM_ME + 256u)
__global__ void __launch_bounds__(256, 2)
kmax_kernel(const float* __restrict__ k, const float* __restrict__ w) {
    extern __shared__ __align__(16) char sm[];
    const u32 smb = smem_u32(sm);
    const int tid = threadIdx.x, wid = tid >> 5;
    const int b = blockIdx.x, s0 = blockIdx.y * 128;
    float* meanc = (float*)(sm + KM_ME);
    if (tid < DD) meanc[tid] = g_mean[b * DD + tid] * (INV_SIGMA / (float)SS);
    __syncthreads();
    stage_row(smb + KM_WH, 0, (const float4*)(w + tid * DD), tid, 1.0f, 0, 0);
    if (tid < 128)
        stage_row(smb + KM_KH, 0, (const float4*)(k + (size_t)(b * SS + s0 + tid) * DD),
                  tid, INV_SIGMA, meanc, 0);
    __syncthreads();
    float mx = -3.0e38f;
    const u32 aB[1] = { smb + KM_KH + (u32)(wid * 16) * 144u };
    for (int ch = 0; ch < 4; ch++) {
        float acc[8][4];
#pragma unroll
        for (int nt = 0; nt < 8; nt++)
#pragma unroll
            for (int j = 0; j < 4; j++) acc[nt][j] = 0.0f;
        const u32 bB[1] = { smb + KM_WH + (u32)(ch * 64) * 144u };
        mma_chunk1(acc, aB, bB, 1, 4, 144u, 144u);
#pragma unroll
        for (int nt = 0; nt < 8; nt++)
#pragma unroll
            for (int j = 0; j < 4; j++) mx = fmaxf(mx, acc[nt][j]);
    }
    mx = fmaxf(mx, __shfl_xor_sync(~0u, mx, 16));
    mx = fmaxf(mx, __shfl_xor_sync(~0u, mx, 8));
    mx = fmaxf(mx, __shfl_xor_sync(~0u, mx, 4));
    mx = fmaxf(mx, __shfl_xor_sync(~0u, mx, 2));
    mx = fmaxf(mx, __shfl_xor_sync(~0u, mx, 1));
    if ((tid & 31) == 0) atomicMax(&g_kmax[b], enc_max(mx));
}

// ---------------- kv: KV[d,f] (+ksum) = (phi_k^T @ [V | 1])^T -----------------
#define KV_WH 0u
#define KV_WL 18432u
#define KV_KH 36864u
#define KV_KL 55296u
#define KV_PTH 73728u
#define KV_PTL 108544u
#define KV_VTH 143360u
#define KV_VTL 162944u
#define KV_ME 182528u
#define KV_NS 182784u
#define KV_SMEM (KV_NS + 512u)
__global__ void __launch_bounds__(256, 1)
kv_kernel(const float* __restrict__ k, const float* __restrict__ v, const float* __restrict__ w) {
    extern __shared__ __align__(16) char sm[];
    const u32 smb = smem_u32(sm);
    const int tid = threadIdx.x, wid = tid >> 5, lane = tid & 31;
    const int b = blockIdx.x, F0 = blockIdx.y * 128;
    float* meanc = (float*)(sm + KV_ME);
    float* nsqs  = (float*)(sm + KV_NS);
    if (tid < DD) meanc[tid] = g_mean[b * DD + tid] * (INV_SIGMA / (float)SS);
    const float gmax = dec_max(g_kmax[b]);
    if (tid < 128)
        stage_row(smb + KV_WH, smb + KV_WL, (const float4*)(w + (F0 + tid) * DD), tid, 1.0f, 0, 0);
    // ones rows d=64..71 of V^T (persist across tiles)
    if (tid >= 128 && tid < 136) {
        u32 rb = (u32)(64 + tid - 128) * 272u;
        for (int s = 0; s < 128; s++) {
            sts16(smb + KV_VTH + rb + 2u * s, (unsigned short)0x3F80u);
            sts16(smb + KV_VTL + rb + 2u * s, (unsigned short)0u);
        }
    }
    __syncthreads();

    float kva[9][4];
#pragma unroll
    for (int nt = 0; nt < 9; nt++)
#pragma unroll
        for (int j = 0; j < 4; j++) kva[nt][j] = 0.0f;

    for (int t = 0; t < 8; t++) {
        const int s0 = (blockIdx.z * 8 + t) * 128;
        if (tid < 128) {       // stage K rows
            float nsq;
            stage_row(smb + KV_KH, smb + KV_KL,
                      (const float4*)(k + (size_t)(b * SS + s0 + tid) * DD), tid, INV_SIGMA, meanc, &nsq);
            nsqs[tid] = nsq;
        } else {               // transpose V rows into V^T columns
            const int sv = tid - 128;
            const float4* vr = (const float4*)(v + (size_t)(b * SS + s0 + sv) * DD);
            const u32 cofs = 2u * (u32)sv;
#pragma unroll
            for (int i = 0; i < 16; i++) {
                float4 x = vr[i];
                unsigned short h0, l0, h1, l1, h2, l2, h3, l3;
                split1(x.x, h0, l0); split1(x.y, h1, l1);
                split1(x.z, h2, l2); split1(x.w, h3, l3);
                sts16(smb + KV_VTH + (u32)(4*i+0) * 272u + cofs, h0);
                sts16(smb + KV_VTH + (u32)(4*i+1) * 272u + cofs, h1);
                sts16(smb + KV_VTH + (u32)(4*i+2) * 272u + cofs, h2);
                sts16(smb + KV_VTH + (u32)(4*i+3) * 272u + cofs, h3);
                sts16(smb + KV_VTL + (u32)(4*i+0) * 272u + cofs, l0);
                sts16(smb + KV_VTL + (u32)(4*i+1) * 272u + cofs, l1);
                sts16(smb + KV_VTL + (u32)(4*i+2) * 272u + cofs, l2);
                sts16(smb + KV_VTL + (u32)(4*i+3) * 272u + cofs, l3);
            }
        }
        __syncthreads();
        // proj: each warp 16 s-rows; 2 chunks of 64 f; 3-pass hi/lo
        const u32 aB[3] = { smb + KV_KH + (u32)(wid * 16) * 144u,
                            smb + KV_KH + (u32)(wid * 16) * 144u,
                            smb + KV_KL + (u32)(wid * 16) * 144u };
        const int r0 = wid * 16 + (lane >> 2);
        const float n0 = nsqs[r0] + gmax, n1 = nsqs[r0 + 8] + gmax;
        for (int ch = 0; ch < 2; ch++) {
            float acc[8][4];
#pragma unroll
            for (int nt = 0; nt < 8; nt++)
#pragma unroll
                for (int j = 0; j < 4; j++) acc[nt][j] = 0.0f;
            const u32 bB[3] = { smb + KV_WH + (u32)(ch * 64) * 144u,
                                smb + KV_WL + (u32)(ch * 64) * 144u,
                                smb + KV_WH + (u32)(ch * 64) * 144u };
            mma_chunk1(acc, aB, bB, 3, 4, 144u, 144u);
#pragma unroll
            for (int nt = 0; nt < 8; nt++) {
                const int f = ch * 64 + nt * 8 + (lane & 3) * 2;
                float p00 = __expf(acc[nt][0] - n0) * INV_SQRT_F;
                float p01 = __expf(acc[nt][1] - n0) * INV_SQRT_F;
                float p10 = __expf(acc[nt][2] - n1) * INV_SQRT_F;
                float p11 = __expf(acc[nt][3] - n1) * INV_SQRT_F;
                unsigned short h, l;
                split1(p00, h, l);
                sts16(smb + KV_PTH + (u32)f * 272u + 2u * r0, h);
                sts16(smb + KV_PTL + (u32)f * 272u + 2u * r0, l);
                split1(p01, h, l);
                sts16(smb + KV_PTH + (u32)(f + 1) * 272u + 2u * r0, h);
                sts16(smb + KV_PTL + (u32)(f + 1) * 272u + 2u * r0, l);
                split1(p10, h, l);
                sts16(smb + KV_PTH + (u32)f * 272u + 2u * (r0 + 8), h);
                sts16(smb + KV_PTL + (u32)f * 272u + 2u * (r0 + 8), l);
                split1(p11, h, l);
                sts16(smb + KV_PTH + (u32)(f + 1) * 272u + 2u * (r0 + 8), h);
                sts16(smb + KV_PTL + (u32)(f + 1) * 272u + 2u * (r0 + 8), l);
            }
        }
        __syncthreads();
        // kv accumulation: warp owns 16 f rows; k = 128 s; n = 72 (9 tiles)
        {
            const u32 aoff = (u32)(lane & 15) * 272u + (u32)(lane >> 4) * 16u;
            const u32 boff = (u32)(lane & 15) * 272u + (u32)(lane >> 4) * 16u;
            const u32 b2off = (u32)(lane & 7) * 272u + (u32)((lane >> 3) & 1) * 16u;
            const u32 APa[3] = { smb + KV_PTH + (u32)(wid * 16) * 272u,
                                 smb + KV_PTH + (u32)(wid * 16) * 272u,
                                 smb + KV_PTL + (u32)(wid * 16) * 272u };
            const u32 BPa[3] = { smb + KV_VTH, smb + KV_VTL, smb + KV_VTH };
            for (int p = 0; p < 3; p++) {
                for (int kk = 0; kk < 8; kk++) {
                    u32 a0, a1, a2, a3;
                    ldsm4(APa[p] + aoff + (u32)kk * 32u, a0, a1, a2, a3);
                    u32 bf[9][2];
#pragma unroll
                    for (int ntp = 0; ntp < 4; ntp++) {
                        u32 r0v, r1v, r2v, r3v;
                        ldsm4(BPa[p] + boff + (u32)ntp * 16u * 272u + (u32)kk * 32u, r0v, r1v, r2v, r3v);
                        bf[2*ntp][0] = r0v; bf[2*ntp][1] = r2v;
                        bf[2*ntp+1][0] = r1v; bf[2*ntp+1][1] = r3v;
                    }
                    ldsm2(BPa[p] + b2off + 64u * 272u + (u32)kk * 32u, bf[8][0], bf[8][1]);
#pragma unroll
                    for (int nt = 0; nt < 9; nt++)
                        mma16816(kva[nt], a0, a1, a2, a3, bf[nt][0], bf[nt][1]);
                }
            }
        }
        __syncthreads();
    }
    // epilogue: scatter KV^T and ksum
    {
        const int f0 = F0 + wid * 16 + (lane >> 2);
#pragma unroll
        for (int nt = 0; nt < 9; nt++) {
            const int d = nt * 8 + (lane & 3) * 2;
            if (nt < 8) {
                atomicAdd(g_kvT + ((size_t)b * DD + d)     * FF + f0,      kva[nt][0]);
                atomicAdd(g_kvT + ((size_t)b * DD + d + 1) * FF + f0,      kva[nt][1]);
                atomicAdd(g_kvT + ((size_t)b * DD + d)     * FF + f0 + 8,  kva[nt][2]);
                atomicAdd(g_kvT + ((size_t)b * DD + d + 1) * FF + f0 + 8,  kva[nt][3]);
            } else if ((lane & 3) == 0) {
                atomicAdd(g_ksum + b * FF + f0,     kva[nt][0]);
                atomicAdd(g_ksum + b * FF + f0 + 8, kva[nt][2]);
            }
        }
    }
}

// ---------------- out: phi_q @ KV^T / deno ------------------------------------
#define OU_WH 0u
#define OU_WL 36864u
#define OU_QH 73728u
#define OU_QL 92160u
#define OU_PH 110592u
#define OU_PL 129024u
#define OU_KVH 147456u
#define OU_KVL 181248u
#define OU_KS 215040u
#define OU_NS 216064u
#define OU_RM 216576u
#define OU_DE 217088u
#define OU_SMEM (OU_DE + 512u)
__global__ void __launch_bounds__(256, 1)
out_kernel(const float* __restrict__ q, const float* __restrict__ w, float* __restrict__ out) {
    extern __shared__ __align__(16) char sm[];
    const u32 smb = smem_u32(sm);
    const int tid = threadIdx.x, wid = tid >> 5, lane = tid & 31;
    const int b = blockIdx.x, s0 = blockIdx.y * 128;
    float* ksum_s = (float*)(sm + OU_KS);
    float* nsqs   = (float*)(sm + OU_NS);
    float* rowmax = (float*)(sm + OU_RM);
    float* denos  = (float*)(sm + OU_DE);
    ksum_s[tid] = g_ksum[b * FF + tid];
    stage_row(smb + OU_WH, smb + OU_WL, (const float4*)(w + tid * DD), tid, 1.0f, 0, 0);
    if (tid < 128) {
        float nsq;
        stage_row(smb + OU_QH, smb + OU_QL, (const float4*)(q + (size_t)(b * SS + s0 + tid) * DD),
                  tid, INV_SIGMA, 0, &nsq);
        nsqs[tid] = nsq;
    } else {   // KV^T tile [d][f] hi/lo, pitch 528
        const int d = (tid - 128) >> 1, half = tid & 1;
        const float* src = g_kvT + (size_t)b * DD * FF + d * FF + half * 128;
        const u32 rb = (u32)d * 528u + (u32)half * 256u;
#pragma unroll 8
        for (int j = 0; j < 64; j++) {
            u32 hi, lo;
            split2(src[2*j], src[2*j+1], hi, lo);
            sts32(smb + OU_KVH + rb + 4u * j, hi);
            sts32(smb + OU_KVL + rb + 4u * j, lo);
        }
    }
    __syncthreads();

    const u32 aH1[1] = { smb + OU_QH + (u32)(wid * 16) * 144u };
    const u32 aB[3]  = { smb + OU_QH + (u32)(wid * 16) * 144u,
                         smb + OU_QH + (u32)(wid * 16) * 144u,
                         smb + OU_QL + (u32)(wid * 16) * 144u };
    const int r0 = wid * 16 + (lane >> 2);
    // pass 1: row max (1-pass bf16; per-row shift cancels in num/deno)
    {
        float mx0 = -3.0e38f, mx1 = -3.0e38f;
        for (int ch = 0; ch < 4; ch++) {
            float acc[8][4];
#pragma unroll
            for (int nt = 0; nt < 8; nt++)
#pragma unroll
                for (int j = 0; j < 4; j++) acc[nt][j] = 0.0f;
            const u32 bB[1] = { smb + OU_WH + (u32)(ch * 64) * 144u };
            mma_chunk1(acc, aH1, bB, 1, 4, 144u, 144u);
#pragma unroll
            for (int nt = 0; nt < 8; nt++) {
                mx0 = fmaxf(mx0, fmaxf(acc[nt][0], acc[nt][1]));
                mx1 = fmaxf(mx1, fmaxf(acc[nt][2], acc[nt][3]));
            }
        }
        mx0 = fmaxf(mx0, __shfl_xor_sync(~0u, mx0, 1));
        mx0 = fmaxf(mx0, __shfl_xor_sync(~0u, mx0, 2));
        mx1 = fmaxf(mx1, __shfl_xor_sync(~0u, mx1, 1));
        mx1 = fmaxf(mx1, __shfl_xor_sync(~0u, mx1, 2));
        if ((lane & 3) == 0) { rowmax[r0] = mx0; rowmax[r0 + 8] = mx1; }
    }
    __syncthreads();

    float oacc[8][4];
#pragma unroll
    for (int nt = 0; nt < 8; nt++)
#pragma unroll
        for (int j = 0; j < 4; j++) oacc[nt][j] = 0.0f;
    float dp0 = 0.0f, dp1 = 0.0f;
    const float n0 = nsqs[r0] + rowmax[r0], n1 = nsqs[r0 + 8] + rowmax[r0 + 8];

    for (int ch = 0; ch < 4; ch++) {
        float acc[8][4];
#pragma unroll
        for (int nt = 0; nt < 8; nt++)
#pragma unroll
            for (int j = 0; j < 4; j++) acc[nt][j] = 0.0f;
        const u32 bB[3] = { smb + OU_WH + (u32)(ch * 64) * 144u,
                            smb + OU_WL + (u32)(ch * 64) * 144u,
                            smb + OU_WH + (u32)(ch * 64) * 144u };
        mma_chunk1(acc, aB, bB, 3, 4, 144u, 144u);
#pragma unroll
        for (int nt = 0; nt < 8; nt++) {
            const int fl = nt * 8 + (lane & 3) * 2;
            const float ks0 = ksum_s[ch * 64 + fl], ks1 = ksum_s[ch * 64 + fl + 1];
            float p00 = __expf(acc[nt][0] - n0) * INV_SQRT_F;
            float p01 = __expf(acc[nt][1] - n0) * INV_SQRT_F;
            float p10 = __expf(acc[nt][2] - n1) * INV_SQRT_F;
            float p11 = __expf(acc[nt][3] - n1) * INV_SQRT_F;
            dp0 += p00 * ks0 + p01 * ks1;
            dp1 += p10 * ks0 + p11 * ks1;
            u32 hi, lo;
            split2(p00, p01, hi, lo);
            sts32(smb + OU_PH + (u32)r0 * 144u + 2u * fl, hi);
            sts32(smb + OU_PL + (u32)r0 * 144u + 2u * fl, lo);
            split2(p10, p11, hi, lo);
            sts32(smb + OU_PH + (u32)(r0 + 8) * 144u + 2u * fl, hi);
            sts32(smb + OU_PL + (u32)(r0 + 8) * 144u + 2u * fl, lo);
        }
        __syncthreads();
        const u32 pA[3] = { smb + OU_PH + (u32)(wid * 16) * 144u,
                            smb + OU_PH + (u32)(wid * 16) * 144u,
                            smb + OU_PL + (u32)(wid * 16) * 144u };
        const u32 pB[3] = { smb + OU_KVH + (u32)(ch * 128), smb + OU_KVL + (u32)(ch * 128),
                            smb + OU_KVH + (u32)(ch * 128) };
        mma_chunk1(oacc, pA, pB, 3, 4, 144u, 528u);
        __syncthreads();
    }
    // deno
    dp0 += __shfl_xor_sync(~0u, dp0, 1);
    dp0 += __shfl_xor_sync(~0u, dp0, 2);
    dp1 += __shfl_xor_sync(~0u, dp1, 1);
    dp1 += __shfl_xor_sync(~0u, dp1, 2);
    if ((lane & 3) == 0) {
        denos[r0]     = fmaxf(dp0, 1e-4f);
        denos[r0 + 8] = fmaxf(dp1, 1e-4f);
    }
    __syncthreads();
    {
        const float i0 = 1.0f / denos[r0], i1 = 1.0f / denos[r0 + 8];
#pragma unroll
        for (int nt = 0; nt < 8; nt++) {
            const int d = nt * 8 + (lane & 3) * 2;
            *(float2*)(out + (size_t)(b * SS + s0 + r0) * DD + d) =
                make_float2(oacc[nt][0] * i0, oacc[nt][1] * i0);
            *(float2*)(out + (size_t)(b * SS + s0 + r0 + 8) * DD + d) =
                make_float2(oacc[nt][2] * i1, oacc[nt][3] * i1);
        }
    }
}

// ---------------- launch ------------------------------------------------------
extern "C" void kernel_launch(void* const* d_in, const int* in_sizes, int n_in,
                              void* d_out, int out_size) {
    const float* q = (const float*)d_in[0];
    const float* k = (const float*)d_in[1];
    const float* v = (const float*)d_in[2];
    const float* w = (const float*)d_in[3];
    float* out = (float*)d_out;
    cudaFuncSetAttribute(kmax_kernel, cudaFuncAttributeMaxDynamicSharedMemorySize, KM_SMEM);
    cudaFuncSetAttribute(kv_kernel,   cudaFuncAttributeMaxDynamicSharedMemorySize, KV_SMEM);
    cudaFuncSetAttribute(out_kernel,  cudaFuncAttributeMaxDynamicSharedMemorySize, OU_SMEM);
    init_kernel<<<(BB * DD * FF + 255) / 256, 256>>>();
    mean_kernel<<<dim3(BB, 4), 256>>>(k);
    kmax_kernel<<<dim3(BB, SS / 128), 256, KM_SMEM>>>(k, w);
    kv_kernel<<<dim3(BB, 2, 4), 256, KV_SMEM>>>(k, v, w);
    out_kernel<<<dim3(BB, SS / 128), 256, OU_SMEM>>>(q, w, out);
}

// round 6
// speedup vs baseline: 2.4853x; 1.0573x over previous
#include <cuda_runtime.h>
#include <cuda_bf16.h>

typedef unsigned u32; typedef unsigned long long u64;
#define BB 64
#define SS 4096
#define DD 64
#define FF 256
#define INV_SIGMA 0.3535533905932738f
#define INV_SQRT_F 0.0625f

__device__ float    g_mean[BB * DD];
__device__ float    g_kvT [BB * DD * FF];   // [b][d][f]
__device__ float    g_ksum[BB * FF];
__device__ unsigned g_kmax[BB];

// ---------------- helpers ----------------------------------------------------
__device__ __forceinline__ u32 smem_u32(const void* p) {
    u32 a; asm("{ .reg .u64 t; cvta.to.shared.u64 t, %1; cvt.u32.u64 %0, t; }" : "=r"(a) : "l"(p));
    return a;
}
__device__ __forceinline__ void sts32(u32 a, u32 v) {
    asm volatile("st.shared.b32 [%0], %1;" :: "r"(a), "r"(v) : "memory");
}
__device__ __forceinline__ void split2(float a, float b, u32& hi, u32& lo) {
    u32 h; asm("cvt.rn.bf16x2.f32 %0,%1,%2;" : "=r"(h) : "f"(b), "f"(a));
    float ah = __uint_as_float(h << 16), bh = __uint_as_float(h & 0xffff0000u);
    float ar = a - ah, br = b - bh;
    asm("cvt.rn.bf16x2.f32 %0,%1,%2;" : "=r"(lo) : "f"(br), "f"(ar));
    hi = h;
}
__device__ __forceinline__ unsigned enc_max(float x) {
    unsigned b = __float_as_uint(x);
    return (b & 0x80000000u) ? ~b : (b | 0x80000000u);
}
__device__ __forceinline__ float dec_max(unsigned k) {
    return (k & 0x80000000u) ? __uint_as_float(k & 0x7FFFFFFFu) : __uint_as_float(~k);
}
__device__ __forceinline__ void ldsm4(u32 a, u32& r0, u32& r1, u32& r2, u32& r3) {
    asm volatile("ldmatrix.sync.aligned.m8n8.x4.shared.b16 {%0,%1,%2,%3}, [%4];"
                 : "=r"(r0), "=r"(r1), "=r"(r2), "=r"(r3) : "r"(a));
}
__device__ __forceinline__ void ldsm4t(u32 a, u32& r0, u32& r1, u32& r2, u32& r3) {
    asm volatile("ldmatrix.sync.aligned.m8n8.x4.trans.shared.b16 {%0,%1,%2,%3}, [%4];"
                 : "=r"(r0), "=r"(r1), "=r"(r2), "=r"(r3) : "r"(a));
}
__device__ __forceinline__ void ldsm2t(u32 a, u32& r0, u32& r1) {
    asm volatile("ldmatrix.sync.aligned.m8n8.x2.trans.shared.b16 {%0,%1}, [%2];"
                 : "=r"(r0), "=r"(r1) : "r"(a));
}
__device__ __forceinline__ void mma16816(float* c, u32 a0, u32 a1, u32 a2, u32 a3, u32 b0, u32 b1) {
    asm volatile("mma.sync.aligned.m16n8k16.row.col.f32.bf16.bf16.f32 "
                 "{%0,%1,%2,%3},{%4,%5,%6,%7},{%8,%9},{%0,%1,%2,%3};"
                 : "+f"(c[0]), "+f"(c[1]), "+f"(c[2]), "+f"(c[3])
                 : "r"(a0), "r"(a1), "r"(a2), "r"(a3), "r"(b0), "r"(b1));
}

// stage one 64-float row as bf16 hi(/lo) into pitch-144B tile at row r
__device__ __forceinline__ void stage_row(u32 hB, u32 lB, const float4* src, int r, float scale,
                                          const float* cen, float* nsq_out) {
    u32 rb = (u32)r * 144u;
    float nsq = 0.0f;
#pragma unroll
    for (int i = 0; i < 16; i++) {
        float4 x = src[i];
        float c0 = x.x * scale, c1 = x.y * scale, c2 = x.z * scale, c3 = x.w * scale;
        if (cen) { c0 -= cen[4*i]; c1 -= cen[4*i+1]; c2 -= cen[4*i+2]; c3 -= cen[4*i+3]; }
        nsq += c0*c0 + c1*c1 + c2*c2 + c3*c3;
        u32 h0, l0, h1, l1;
        split2(c0, c1, h0, l0); split2(c2, c3, h1, l1);
        sts32(hB + rb + i * 8u, h0); sts32(hB + rb + i * 8u + 4u, h1);
        if (lB) { sts32(lB + rb + i * 8u, l0); sts32(lB + rb + i * 8u + 4u, l1); }
    }
    if (nsq_out) *nsq_out = 0.5f * nsq;
}

// 1-pass chunk GEMM (hi only): acc[8 nt][4]; warp m-tile 16 rows; k = nk*16
__device__ __forceinline__ void mma_chunk1(float (&acc)[8][4], u32 aH, u32 bH,
                                           int nk, u32 apitch, u32 bpitch) {
    const int lane = threadIdx.x & 31;
    const u32 aoff = (u32)(lane & 15) * apitch + (u32)(lane >> 4) * 16u;
    const u32 boff = (u32)(lane & 15) * bpitch + (u32)(lane >> 4) * 16u;
    for (int kk = 0; kk < nk; kk++) {
        u32 a0, a1, a2, a3;
        ldsm4(aH + aoff + (u32)kk * 32u, a0, a1, a2, a3);
#pragma unroll
        for (int ntp = 0; ntp < 4; ntp++) {
            u32 h0, h1, h2, h3;
            ldsm4(bH + boff + (u32)ntp * 16u * bpitch + (u32)kk * 32u, h0, h1, h2, h3);
            mma16816(acc[2*ntp],   a0, a1, a2, a3, h0, h2);
            mma16816(acc[2*ntp+1], a0, a1, a2, a3, h1, h3);
        }
    }
}

// fused 3-pass hi/lo chunk GEMM: loads each fragment once, issues HH + HL + LH
__device__ __forceinline__ void mma_chunk_hl(float (&acc)[8][4], u32 aH, u32 aL,
                                             u32 bH, u32 bL, int nk, u32 apitch, u32 bpitch) {
    const int lane = threadIdx.x & 31;
    const u32 aoff = (u32)(lane & 15) * apitch + (u32)(lane >> 4) * 16u;
    const u32 boff = (u32)(lane & 15) * bpitch + (u32)(lane >> 4) * 16u;
    for (int kk = 0; kk < nk; kk++) {
        u32 ah0, ah1, ah2, ah3, al0, al1, al2, al3;
        ldsm4(aH + aoff + (u32)kk * 32u, ah0, ah1, ah2, ah3);
        ldsm4(aL + aoff + (u32)kk * 32u, al0, al1, al2, al3);
#pragma unroll
        for (int ntp = 0; ntp < 4; ntp++) {
            u32 h0, h1, h2, h3, l0, l1, l2, l3;
            ldsm4(bH + boff + (u32)ntp * 16u * bpitch + (u32)kk * 32u, h0, h1, h2, h3);
            ldsm4(bL + boff + (u32)ntp * 16u * bpitch + (u32)kk * 32u, l0, l1, l2, l3);
            mma16816(acc[2*ntp],   ah0, ah1, ah2, ah3, h0, h2);
            mma16816(acc[2*ntp],   ah0, ah1, ah2, ah3, l0, l2);
            mma16816(acc[2*ntp],   al0, al1, al2, al3, h0, h2);
            mma16816(acc[2*ntp+1], ah0, ah1, ah2, ah3, h1, h3);
            mma16816(acc[2*ntp+1], ah0, ah1, ah2, ah3, l1, l3);
            mma16816(acc[2*ntp+1], al0, al1, al2, al3, h1, h3);
        }
    }
}

// ---------------- init + mean ------------------------------------------------
__global__ void init_kernel() {
    int i = blockIdx.x * 256 + threadIdx.x;
    if (i < BB * DD * FF) g_kvT[i] = 0.0f;
    if (i < BB * FF)      g_ksum[i] = 0.0f;
    if (i < BB * DD)      g_mean[i] = 0.0f;
    if (i < BB)           g_kmax[i] = 0x007FFFFFu;
}
__global__ void mean_kernel(const float* __restrict__ k) {
    const int b = blockIdx.x, p = blockIdx.y;
    const int d = threadIdx.x & 63, sub = threadIdx.x >> 6;
    const float* kp = k + (size_t)(b * SS + p * 1024) * DD;
    float s = 0.0f;
    for (int r = sub; r < 1024; r += 4) s += kp[r * DD + d];
    __shared__ float sm[4][DD];
    sm[sub][d] = s; __syncthreads();
    if (threadIdx.x < DD)
        atomicAdd(&g_mean[b * DD + threadIdx.x],
                  sm[0][threadIdx.x] + sm[1][threadIdx.x] + sm[2][threadIdx.x] + sm[3][threadIdx.x]);
}

// ---------------- kmax: max over Kc @ W^T (1-pass bf16; shift cancels exactly) -
#define KM_WH 0u
#define KM_KH 36864u
#define KM_ME 55296u
#define KM_SMEM (KM_ME + 256u)
__global__ void __launch_bounds__(256, 2)
kmax_kernel(const float* __restrict__ k, const float* __restrict__ w) {
    extern __shared__ __align__(16) char sm[];
    const u32 smb = smem_u32(sm);
    const int tid = threadIdx.x, wid = tid >> 5;
    const int b = blockIdx.x, s0 = blockIdx.y * 128;
    float* meanc = (float*)(sm + KM_ME);
    if (tid < DD) meanc[tid] = g_mean[b * DD + tid] * (INV_SIGMA / (float)SS);
    __syncthreads();
    stage_row(smb + KM_WH, 0, (const float4*)(w + tid * DD), tid, 1.0f, 0, 0);
    if (tid < 128)
        stage_row(smb + KM_KH, 0, (const float4*)(k + (size_t)(b * SS + s0 + tid) * DD),
                  tid, INV_SIGMA, meanc, 0);
    __syncthreads();
    float mx = -3.0e38f;
    const u32 aB = smb + KM_KH + (u32)(wid * 16) * 144u;
    for (int ch = 0; ch < 4; ch++) {
        float acc[8][4];
#pragma unroll
        for (int nt = 0; nt < 8; nt++)
#pragma unroll
            for (int j = 0; j < 4; j++) acc[nt][j] = 0.0f;
        mma_chunk1(acc, aB, smb + KM_WH + (u32)(ch * 64) * 144u, 4, 144u, 144u);
#pragma unroll
        for (int nt = 0; nt < 8; nt++)
#pragma unroll
            for (int j = 0; j < 4; j++) mx = fmaxf(mx, acc[nt][j]);
    }
    mx = fmaxf(mx, __shfl_xor_sync(~0u, mx, 16));
    mx = fmaxf(mx, __shfl_xor_sync(~0u, mx, 8));
    mx = fmaxf(mx, __shfl_xor_sync(~0u, mx, 4));
    mx = fmaxf(mx, __shfl_xor_sync(~0u, mx, 2));
    mx = fmaxf(mx, __shfl_xor_sync(~0u, mx, 1));
    if ((tid & 31) == 0) atomicMax(&g_kmax[b], enc_max(mx));
}

// ---------------- kv: KV[d,f] (+ksum) = (phi_k^T @ [V | 1])^T -----------------
// phi kept in natural [s][f] layout (pitch 272); V row-major [s][72] (pitch 144)
// with ones-columns d=64..71; kv MMA uses ldmatrix.trans for both operands.
#define KV_WH 0u
#define KV_WL 18432u
#define KV_KH 36864u
#define KV_KL 55296u
#define KV_PH 73728u
#define KV_PL 108544u
#define KV_VH 143360u
#define KV_VL 161792u
#define KV_ME 180224u
#define KV_NS 180480u
#define KV_SMEM (KV_NS + 512u)
__global__ void __launch_bounds__(256, 1)
kv_kernel(const float* __restrict__ k, const float* __restrict__ v, const float* __restrict__ w) {
    extern __shared__ __align__(16) char sm[];
    const u32 smb = smem_u32(sm);
    const int tid = threadIdx.x, wid = tid >> 5, lane = tid & 31;
    const int b = blockIdx.x, F0 = blockIdx.y * 128;
    float* meanc = (float*)(sm + KV_ME);
    float* nsqs  = (float*)(sm + KV_NS);
    if (tid < DD) meanc[tid] = g_mean[b * DD + tid] * (INV_SIGMA / (float)SS);
    const float gmax = dec_max(g_kmax[b]);
    if (tid < 128)
        stage_row(smb + KV_WH, smb + KV_WL, (const float4*)(w + (F0 + tid) * DD), tid, 1.0f, 0, 0);
    __syncthreads();

    float kva[9][4];
#pragma unroll
    for (int nt = 0; nt < 9; nt++)
#pragma unroll
        for (int j = 0; j < 4; j++) kva[nt][j] = 0.0f;

    for (int t = 0; t < 8; t++) {
        const int s0 = (blockIdx.z * 8 + t) * 128;
        if (tid < 128) {       // stage K rows (hi/lo, pitch 144)
            float nsq;
            stage_row(smb + KV_KH, smb + KV_KL,
                      (const float4*)(k + (size_t)(b * SS + s0 + tid) * DD), tid, INV_SIGMA, meanc, &nsq);
            nsqs[tid] = nsq;
        } else {               // stage V row [s][72] + ones cols (coalesced)
            const int sv = tid - 128;
            const float4* vr = (const float4*)(v + (size_t)(b * SS + s0 + sv) * DD);
            const u32 rb = (u32)sv * 144u;
#pragma unroll
            for (int i = 0; i < 16; i++) {
                float4 x = vr[i];
                u32 h0, l0, h1, l1;
                split2(x.x, x.y, h0, l0); split2(x.z, x.w, h1, l1);
                sts32(smb + KV_VH + rb + i * 8u,      h0);
                sts32(smb + KV_VH + rb + i * 8u + 4u, h1);
                sts32(smb + KV_VL + rb + i * 8u,      l0);
                sts32(smb + KV_VL + rb + i * 8u + 4u, l1);
            }
#pragma unroll
            for (int j = 0; j < 4; j++) {
                sts32(smb + KV_VH + rb + 128u + 4u * j, 0x3F803F80u);
                sts32(smb + KV_VL + rb + 128u + 4u * j, 0u);
            }
        }
        __syncthreads();
        // proj: each warp 16 s-rows; 2 chunks of 64 f; fused 3-pass hi/lo
        const int r0 = wid * 16 + (lane >> 2);
        const float n0 = nsqs[r0] + gmax, n1 = nsqs[r0 + 8] + gmax;
        for (int ch = 0; ch < 2; ch++) {
            float acc[8][4];
#pragma unroll
            for (int nt = 0; nt < 8; nt++)
#pragma unroll
                for (int j = 0; j < 4; j++) acc[nt][j] = 0.0f;
            mma_chunk_hl(acc, smb + KV_KH + (u32)(wid * 16) * 144u,
                              smb + KV_KL + (u32)(wid * 16) * 144u,
                              smb + KV_WH + (u32)(ch * 64) * 144u,
                              smb + KV_WL + (u32)(ch * 64) * 144u, 4, 144u, 144u);
            // exp + store phi natural [s][f] (conflict-free sts32 pairs)
#pragma unroll
            for (int nt = 0; nt < 8; nt++) {
                const int f = ch * 64 + nt * 8 + (lane & 3) * 2;
                float p00 = __expf(acc[nt][0] - n0) * INV_SQRT_F;
                float p01 = __expf(acc[nt][1] - n0) * INV_SQRT_F;
                float p10 = __expf(acc[nt][2] - n1) * INV_SQRT_F;
                float p11 = __expf(acc[nt][3] - n1) * INV_SQRT_F;
                u32 hi, lo;
                split2(p00, p01, hi, lo);
                sts32(smb + KV_PH + (u32)r0 * 272u + 2u * f, hi);
                sts32(smb + KV_PL + (u32)r0 * 272u + 2u * f, lo);
                split2(p10, p11, hi, lo);
                sts32(smb + KV_PH + (u32)(r0 + 8) * 272u + 2u * f, hi);
                sts32(smb + KV_PL + (u32)(r0 + 8) * 272u + 2u * f, lo);
            }
        }
        __syncthreads();
        // kv accumulation: A = phi^T (trans loads), B = V^T (trans loads); k = 128 s
        {
            const u32 aoff = ((u32)(lane & 7) + (u32)((lane >> 4) & 1) * 8u) * 272u +
                             (u32)((lane >> 3) & 1) * 16u + (u32)wid * 32u;
            const u32 boff = ((u32)(lane & 7) + (u32)((lane >> 3) & 1) * 8u) * 144u +
                             (u32)((lane >> 4) & 1) * 16u;
            const u32 b2off = ((u32)(lane & 7) + (u32)((lane >> 3) & 1) * 8u) * 144u + 128u;
            const u32 PHb = smb + KV_PH, PLb = smb + KV_PL;
            const u32 VHb = smb + KV_VH, VLb = smb + KV_VL;
            for (int kk = 0; kk < 8; kk++) {
                const u32 ka = (u32)kk * 16u * 272u, kb = (u32)kk * 16u * 144u;
                u32 ah0, ah1, ah2, ah3, al0, al1, al2, al3;
                ldsm4t(PHb + aoff + ka, ah0, ah1, ah2, ah3);
                ldsm4t(PLb + aoff + ka, al0, al1, al2, al3);
#pragma unroll
                for (int ntp = 0; ntp < 4; ntp++) {
                    u32 h0, h1, h2, h3, l0, l1, l2, l3;
                    ldsm4t(VHb + boff + (u32)ntp * 32u + kb, h0, h1, h2, h3);
                    ldsm4t(VLb + boff + (u32)ntp * 32u + kb, l0, l1, l2, l3);
                    mma16816(kva[2*ntp],   ah0, ah1, ah2, ah3, h0, h1);
                    mma16816(kva[2*ntp],   ah0, ah1, ah2, ah3, l0, l1);
                    mma16816(kva[2*ntp],   al0, al1, al2, al3, h0, h1);
                    mma16816(kva[2*ntp+1], ah0, ah1, ah2, ah3, h2, h3);
                    mma16816(kva[2*ntp+1], ah0, ah1, ah2, ah3, l2, l3);
                    mma16816(kva[2*ntp+1], al0, al1, al2, al3, h2, h3);
                }
                u32 o0, o1;
                ldsm2t(VHb + b2off + kb, o0, o1);
                mma16816(kva[8], ah0, ah1, ah2, ah3, o0, o1);
                mma16816(kva[8], al0, al1, al2, al3, o0, o1);
            }
        }
        __syncthreads();
    }
    // epilogue: scatter KV^T and ksum
    {
        const int f0 = F0 + wid * 16 + (lane >> 2);
#pragma unroll
        for (int nt = 0; nt < 9; nt++) {
            const int d = nt * 8 + (lane & 3) * 2;
            if (nt < 8) {
                atomicAdd(g_kvT + ((size_t)b * DD + d)     * FF + f0,      kva[nt][0]);
                atomicAdd(g_kvT + ((size_t)b * DD + d + 1) * FF + f0,      kva[nt][1]);
                atomicAdd(g_kvT + ((size_t)b * DD + d)     * FF + f0 + 8,  kva[nt][2]);
                atomicAdd(g_kvT + ((size_t)b * DD + d + 1) * FF + f0 + 8,  kva[nt][3]);
            } else if ((lane & 3) == 0) {
                atomicAdd(g_ksum + b * FF + f0,     kva[nt][0]);
                atomicAdd(g_ksum + b * FF + f0 + 8, kva[nt][2]);
            }
        }
    }
}

// ---------------- out: phi_q @ KV^T / deno ------------------------------------
#define OU_WH 0u
#define OU_WL 36864u
#define OU_QH 73728u
#define OU_QL 92160u
#define OU_PH 110592u
#define OU_PL 129024u
#define OU_KVH 147456u
#define OU_KVL 181248u
#define OU_KS 215040u
#define OU_NS 216064u
#define OU_RM 216576u
#define OU_DE 217088u
#define OU_SMEM (OU_DE + 512u)
__global__ void __launch_bounds__(256, 1)
out_kernel(const float* __restrict__ q, const float* __restrict__ w, float* __restrict__ out) {
    extern __shared__ __align__(16) char sm[];
    const u32 smb = smem_u32(sm);
    const int tid = threadIdx.x, wid = tid >> 5, lane = tid & 31;
    const int b = blockIdx.x, s0 = blockIdx.y * 128;
    float* ksum_s = (float*)(sm + OU_KS);
    float* nsqs   = (float*)(sm + OU_NS);
    float* rowmax = (float*)(sm + OU_RM);
    float* denos  = (float*)(sm + OU_DE);
    ksum_s[tid] = g_ksum[b * FF + tid];
    stage_row(smb + OU_WH, smb + OU_WL, (const float4*)(w + tid * DD), tid, 1.0f, 0, 0);
    if (tid < 128) {
        float nsq;
        stage_row(smb + OU_QH, smb + OU_QL, (const float4*)(q + (size_t)(b * SS + s0 + tid) * DD),
                  tid, INV_SIGMA, 0, &nsq);
        nsqs[tid] = nsq;
    } else {   // KV^T tile [d][f] hi/lo, pitch 528
        const int d = (tid - 128) >> 1, half = tid & 1;
        const float* src = g_kvT + (size_t)b * DD * FF + d * FF + half * 128;
        const u32 rb = (u32)d * 528u + (u32)half * 256u;
#pragma unroll 8
        for (int j = 0; j < 64; j++) {
            u32 hi, lo;
            split2(src[2*j], src[2*j+1], hi, lo);
            sts32(smb + OU_KVH + rb + 4u * j, hi);
            sts32(smb + OU_KVL + rb + 4u * j, lo);
        }
    }
    __syncthreads();

    const u32 aHb = smb + OU_QH + (u32)(wid * 16) * 144u;
    const u32 aLb = smb + OU_QL + (u32)(wid * 16) * 144u;
    const int r0 = wid * 16 + (lane >> 2);
    // pass 1: row max (1-pass bf16; per-row shift cancels in num/deno)
    {
        float mx0 = -3.0e38f, mx1 = -3.0e38f;
        for (int ch = 0; ch < 4; ch++) {
            float acc[8][4];
#pragma unroll
            for (int nt = 0; nt < 8; nt++)
#pragma unroll
                for (int j = 0; j < 4; j++) acc[nt][j] = 0.0f;
            mma_chunk1(acc, aHb, smb + OU_WH + (u32)(ch * 64) * 144u, 4, 144u, 144u);
#pragma unroll
            for (int nt = 0; nt < 8; nt++) {
                mx0 = fmaxf(mx0, fmaxf(acc[nt][0], acc[nt][1]));
                mx1 = fmaxf(mx1, fmaxf(acc[nt][2], acc[nt][3]));
            }
        }
        mx0 = fmaxf(mx0, __shfl_xor_sync(~0u, mx0, 1));
        mx0 = fmaxf(mx0, __shfl_xor_sync(~0u, mx0, 2));
        mx1 = fmaxf(mx1, __shfl_xor_sync(~0u, mx1, 1));
        mx1 = fmaxf(mx1, __shfl_xor_sync(~0u, mx1, 2));
        if ((lane & 3) == 0) { rowmax[r0] = mx0; rowmax[r0 + 8] = mx1; }
    }
    __syncthreads();

    float oacc[8][4];
#pragma unroll
    for (int nt = 0; nt < 8; nt++)
#pragma unroll
        for (int j = 0; j < 4; j++) oacc[nt][j] = 0.0f;
    float dp0 = 0.0f, dp1 = 0.0f;
    const float n0 = nsqs[r0] + rowmax[r0], n1 = nsqs[r0 + 8] + rowmax[r0 + 8];

    for (int ch = 0; ch < 4; ch++) {
        float acc[8][4];
#pragma unroll
        for (int nt = 0; nt < 8; nt++)
#pragma unroll
            for (int j = 0; j < 4; j++) acc[nt][j] = 0.0f;
        mma_chunk_hl(acc, aHb, aLb, smb + OU_WH + (u32)(ch * 64) * 144u,
                     smb + OU_WL + (u32)(ch * 64) * 144u, 4, 144u, 144u);
#pragma unroll
        for (int nt = 0; nt < 8; nt++) {
            const int fl = nt * 8 + (lane & 3) * 2;
            const float ks0 = ksum_s[ch * 64 + fl], ks1 = ksum_s[ch * 64 + fl + 1];
            float p00 = __expf(acc[nt][0] - n0) * INV_SQRT_F;
            float p01 = __expf(acc[nt][1] - n0) * INV_SQRT_F;
            float p10 = __expf(acc[nt][2] - n1) * INV_SQRT_F;
            float p11 = __expf(acc[nt][3] - n1) * INV_SQRT_F;
            dp0 += p00 * ks0 + p01 * ks1;
            dp1 += p10 * ks0 + p11 * ks1;
            u32 hi, lo;
            split2(p00, p01, hi, lo);
            sts32(smb + OU_PH + (u32)r0 * 144u + 2u * fl, hi);
            sts32(smb + OU_PL + (u32)r0 * 144u + 2u * fl, lo);
            split2(p10, p11, hi, lo);
            sts32(smb + OU_PH + (u32)(r0 + 8) * 144u + 2u * fl, hi);
            sts32(smb + OU_PL + (u32)(r0 + 8) * 144u + 2u * fl, lo);
        }
        __syncthreads();
        mma_chunk_hl(oacc, smb + OU_PH + (u32)(wid * 16) * 144u,
                           smb + OU_PL + (u32)(wid * 16) * 144u,
                           smb + OU_KVH + (u32)(ch * 128), smb + OU_KVL + (u32)(ch * 128),
                     4, 144u, 528u);
        __syncthreads();
    }
    // deno
    dp0 += __shfl_xor_sync(~0u, dp0, 1);
    dp0 += __shfl_xor_sync(~0u, dp0, 2);
    dp1 += __shfl_xor_sync(~0u, dp1, 1);
    dp1 += __shfl_xor_sync(~0u, dp1, 2);
    if ((lane & 3) == 0) {
        denos[r0]     = fmaxf(dp0, 1e-4f);
        denos[r0 + 8] = fmaxf(dp1, 1e-4f);
    }
    __syncthreads();
    {
        const float i0 = 1.0f / denos[r0], i1 = 1.0f / denos[r0 + 8];
#pragma unroll
        for (int nt = 0; nt < 8; nt++) {
            const int d = nt * 8 + (lane & 3) * 2;
            *(float2*)(out + (size_t)(b * SS + s0 + r0) * DD + d) =
                make_float2(oacc[nt][0] * i0, oacc[nt][1] * i0);
            *(float2*)(out + (size_t)(b * SS + s0 + r0 + 8) * DD + d) =
                make_float2(oacc[nt][2] * i1, oacc[nt][3] * i1);
        }
    }
}

// ---------------- launch ------------------------------------------------------
extern "C" void kernel_launch(void* const* d_in, const int* in_sizes, int n_in,
                              void* d_out, int out_size) {
    const float* q = (const float*)d_in[0];
    const float* k = (const float*)d_in[1];
    const float* v = (const float*)d_in[2];
    const float* w = (const float*)d_in[3];
    float* out = (float*)d_out;
    cudaFuncSetAttribute(kmax_kernel, cudaFuncAttributeMaxDynamicSharedMemorySize, KM_SMEM);
    cudaFuncSetAttribute(kv_kernel,   cudaFuncAttributeMaxDynamicSharedMemorySize, KV_SMEM);
    cudaFuncSetAttribute(out_kernel,  cudaFuncAttributeMaxDynamicSharedMemorySize, OU_SMEM);
    init_kernel<<<(BB * DD * FF + 255) / 256, 256>>>();
    mean_kernel<<<dim3(BB, 4), 256>>>(k);
    kmax_kernel<<<dim3(BB, SS / 128), 256, KM_SMEM>>>(k, w);
    kv_kernel<<<dim3(BB, 2, 4), 256, KV_SMEM>>>(k, v, w);
    out_kernel<<<dim3(BB, SS / 128), 256, OU_SMEM>>>(q, w, out);
}